// round 5
// baseline (speedup 1.0000x reference)
#include <cuda_runtime.h>
#include <cuda_bf16.h>
#include <cuda_fp16.h>
#include <math.h>
#include <cstdint>

// Problem constants
#define BATCH 2
#define SEQ   4096
#define EMB   1024
#define HEADS 16
#define HDIM  64
#define MROWS (BATCH*SEQ)   // 8192

// ---------------- scratch (static device globals; no runtime allocation) ----
__device__ float g_Q[(size_t)BATCH*HEADS*SEQ*HDIM];   // (B,H,T,D)
__device__ float g_K[(size_t)BATCH*HEADS*SEQ*HDIM];
__device__ float g_V[(size_t)BATCH*HEADS*SEQ*HDIM];
__device__ float g_AO[(size_t)BATCH*SEQ*EMB];         // (B,T,E) attention output

__device__ __forceinline__ uint32_t f2tf32(float f) {
    uint32_t r;
    asm("cvt.rna.tf32.f32 %0, %1;" : "=r"(r) : "f"(f));
    return r;
}

__device__ __forceinline__ uint32_t pack_h2(float a, float b) {
    __half2 h = __floats2half2_rn(a, b);
    return *(uint32_t*)&h;
}

__device__ __forceinline__ void mma_tf32(
    float& c0, float& c1, float& c2, float& c3,
    uint32_t a0, uint32_t a1, uint32_t a2, uint32_t a3,
    uint32_t b0, uint32_t b1)
{
    asm volatile(
        "mma.sync.aligned.m16n8k8.row.col.f32.tf32.tf32.f32 "
        "{%0,%1,%2,%3}, {%4,%5,%6,%7}, {%8,%9}, {%0,%1,%2,%3};"
        : "+f"(c0), "+f"(c1), "+f"(c2), "+f"(c3)
        : "r"(a0), "r"(a1), "r"(a2), "r"(a3), "r"(b0), "r"(b1));
}

__device__ __forceinline__ void mma_fp16(
    float& c0, float& c1, float& c2, float& c3,
    uint32_t a0, uint32_t a1, uint32_t a2, uint32_t a3,
    uint32_t b0, uint32_t b1)
{
    asm volatile(
        "mma.sync.aligned.m16n8k16.row.col.f32.f16.f16.f32 "
        "{%0,%1,%2,%3}, {%4,%5,%6,%7}, {%8,%9}, {%0,%1,%2,%3};"
        : "+f"(c0), "+f"(c1), "+f"(c2), "+f"(c3)
        : "r"(a0), "r"(a1), "r"(a2), "r"(a3), "r"(b0), "r"(b1));
}

// ============================================================================
// tf32 mma.sync GEMM (unchanged from round 4):
// C[m][n] = sum_k A[m][k] * W[n][k]  (+bias)
// ============================================================================
#define GBM 128
#define GBN 128
#define GBK 32
#define GPAD 36

__global__ __launch_bounds__(256) void gemm_mma(
    const float* __restrict__ A, const float* __restrict__ W,
    const float* __restrict__ bias, float* __restrict__ out,
    int M, int N, int K, int mode)
{
    __shared__ uint32_t As[GBM * GPAD];
    __shared__ uint32_t Bs[GBN * GPAD];

    const int tid = threadIdx.x;
    const int wid = tid >> 5;
    const int lid = tid & 31;
    const int qrow = lid >> 2;
    const int qcol = lid & 3;

    const int row0 = blockIdx.y * GBM;
    const int col0 = blockIdx.x * GBN;
    const int wm0 = (wid & 1) * 64;
    const int wn0 = (wid >> 1) * 32;

    float c[4][4][4];
    #pragma unroll
    for (int i = 0; i < 4; i++)
        #pragma unroll
        for (int j = 0; j < 4; j++)
            #pragma unroll
            for (int f = 0; f < 4; f++) c[i][j][f] = 0.f;

    for (int k0 = 0; k0 < K; k0 += GBK) {
        #pragma unroll
        for (int l = 0; l < 4; l++) {
            int idx = tid + l * 256;
            int r   = idx >> 3;
            int c4  = (idx & 7) * 4;
            float4 va = *(const float4*)&A[(size_t)(row0 + r) * K + k0 + c4];
            *(uint4*)&As[r * GPAD + c4] =
                make_uint4(f2tf32(va.x), f2tf32(va.y), f2tf32(va.z), f2tf32(va.w));
            float4 vb = *(const float4*)&W[(size_t)(col0 + r) * K + k0 + c4];
            *(uint4*)&Bs[r * GPAD + c4] =
                make_uint4(f2tf32(vb.x), f2tf32(vb.y), f2tf32(vb.z), f2tf32(vb.w));
        }
        __syncthreads();

        #pragma unroll
        for (int kk = 0; kk < GBK / 8; kk++) {
            const int kb = kk * 8;
            uint32_t a[4][4], b[4][2];
            #pragma unroll
            for (int mi = 0; mi < 4; mi++) {
                const uint32_t* ap = &As[(wm0 + mi * 16 + qrow) * GPAD + kb + qcol];
                a[mi][0] = ap[0];
                a[mi][1] = ap[8 * GPAD];
                a[mi][2] = ap[4];
                a[mi][3] = ap[8 * GPAD + 4];
            }
            #pragma unroll
            for (int ni = 0; ni < 4; ni++) {
                const uint32_t* bp = &Bs[(wn0 + ni * 8 + qrow) * GPAD + kb + qcol];
                b[ni][0] = bp[0];
                b[ni][1] = bp[4];
            }
            #pragma unroll
            for (int mi = 0; mi < 4; mi++)
                #pragma unroll
                for (int ni = 0; ni < 4; ni++)
                    mma_tf32(c[mi][ni][0], c[mi][ni][1], c[mi][ni][2], c[mi][ni][3],
                             a[mi][0], a[mi][1], a[mi][2], a[mi][3],
                             b[ni][0], b[ni][1]);
        }
        __syncthreads();
    }

    #pragma unroll
    for (int mi = 0; mi < 4; mi++) {
        #pragma unroll
        for (int half = 0; half < 2; half++) {
            const int m = row0 + wm0 + mi * 16 + qrow + half * 8;
            const int bi = m >> 12;
            const int t  = m & (SEQ - 1);
            #pragma unroll
            for (int ni = 0; ni < 4; ni++) {
                const int n = col0 + wn0 + ni * 8 + qcol * 2;
                float v0 = c[mi][ni][half * 2 + 0];
                float v1 = c[mi][ni][half * 2 + 1];
                if (mode == 0) {
                    const int h = n >> 6;
                    const int d = n & (HDIM - 1);
                    *(float2*)&out[(((size_t)bi * HEADS + h) * SEQ + t) * HDIM + d] =
                        make_float2(v0, v1);
                } else {
                    float2 bb = *(const float2*)&bias[n];
                    *(float2*)&out[(size_t)m * N + n] = make_float2(v0 + bb.x, v1 + bb.y);
                }
            }
        }
    }
}

// ============================================================================
// Flash attention on fp16 mma.sync m16n8k16. 4 warps, Br=Bc=64, D=64.
// Ks: [key][d] fp16 pad 72 halves.  Vt: [d][key] fp16 pad 72.  Ps: [q][key].
// All fragment loads bank-conflict-free (bank = 4*qrow + qcol pattern).
// ============================================================================
#define FP 72   // halves per row

__global__ __launch_bounds__(128) void flash_mma(
    const float* __restrict__ Q, const float* __restrict__ K,
    const float* __restrict__ V, float* __restrict__ O)
{
    __shared__ __half Ks[64 * FP];   // [key][d]   (also Q staging)
    __shared__ __half Vt[64 * FP];   // [d][key]
    __shared__ __half Ps[64 * FP];   // [q][key]

    const int qt = blockIdx.x;
    const int bh = blockIdx.y;
    const size_t base = (size_t)bh * SEQ * HDIM;
    const float* Qb = Q + base;
    const float* Kb = K + base;
    const float* Vb = V + base;

    const int tid  = threadIdx.x;
    const int wid  = tid >> 5;
    const int lid  = tid & 31;
    const int qrow = lid >> 2;     // 0..7
    const int qcol = lid & 3;      // 0..3
    const int w16  = wid * 16;
    const int q0   = qt * 64;
    const unsigned FULL = 0xffffffffu;

    // ---- stage Q (scaled) via Ks buffer, pull A-fragments to registers ----
    #pragma unroll
    for (int l = 0; l < 8; l++) {
        int idx = tid + l * 128;
        int r   = idx >> 4;
        int d4  = (idx & 15) * 4;
        float4 v = *(const float4*)&Qb[(size_t)(q0 + r) * HDIM + d4];
        uint2 p = make_uint2(pack_h2(v.x * 0.125f, v.y * 0.125f),
                             pack_h2(v.z * 0.125f, v.w * 0.125f));
        *(uint2*)&Ks[r * FP + d4] = p;
    }
    __syncthreads();

    uint32_t aq[4][4];
    #pragma unroll
    for (int ks = 0; ks < 4; ks++) {
        const __half* p0 = &Ks[(w16 + qrow) * FP + ks * 16 + 2 * qcol];
        const __half* p1 = &Ks[(w16 + qrow + 8) * FP + ks * 16 + 2 * qcol];
        aq[ks][0] = *(const uint32_t*)p0;
        aq[ks][1] = *(const uint32_t*)p1;
        aq[ks][2] = *(const uint32_t*)(p0 + 8);
        aq[ks][3] = *(const uint32_t*)(p1 + 8);
    }
    __syncthreads();

    float o[8][4];
    #pragma unroll
    for (int nt = 0; nt < 8; nt++)
        #pragma unroll
        for (int f = 0; f < 4; f++) o[nt][f] = 0.f;
    float m_lo = -INFINITY, m_hi = -INFINITY, l_lo = 0.f, l_hi = 0.f;

    for (int jt = 0; jt <= qt; jt++) {
        __syncthreads();   // protect Ks/Vt of previous iteration
        // ---- K [key][d]: coalesced loads, 8B row-contiguous stores ----
        #pragma unroll
        for (int l = 0; l < 8; l++) {
            int idx = tid + l * 128;
            int r   = idx >> 4;
            int d4  = (idx & 15) * 4;
            float4 kv = *(const float4*)&Kb[(size_t)(jt * 64 + r) * HDIM + d4];
            *(uint2*)&Ks[r * FP + d4] =
                make_uint2(pack_h2(kv.x, kv.y), pack_h2(kv.z, kv.w));
        }
        // ---- V transposed [d][key]: key-major assignment (spread banks) ----
        #pragma unroll
        for (int l = 0; l < 8; l++) {
            int idx = tid + l * 128;
            int key = idx & 63;
            int d4  = (idx >> 6) * 4;
            float4 vv = *(const float4*)&Vb[(size_t)(jt * 64 + key) * HDIM + d4];
            Vt[(d4 + 0) * FP + key] = __float2half_rn(vv.x);
            Vt[(d4 + 1) * FP + key] = __float2half_rn(vv.y);
            Vt[(d4 + 2) * FP + key] = __float2half_rn(vv.z);
            Vt[(d4 + 3) * FP + key] = __float2half_rn(vv.w);
        }
        __syncthreads();

        // ---- S = Q K^T ----
        float c[8][4];
        #pragma unroll
        for (int nt = 0; nt < 8; nt++)
            #pragma unroll
            for (int f = 0; f < 4; f++) c[nt][f] = 0.f;

        #pragma unroll
        for (int ks = 0; ks < 4; ks++) {
            #pragma unroll
            for (int nt = 0; nt < 8; nt++) {
                const __half* bp = &Ks[(nt * 8 + qrow) * FP + ks * 16 + 2 * qcol];
                mma_fp16(c[nt][0], c[nt][1], c[nt][2], c[nt][3],
                         aq[ks][0], aq[ks][1], aq[ks][2], aq[ks][3],
                         *(const uint32_t*)bp, *(const uint32_t*)(bp + 8));
            }
        }

        // ---- causal mask (diagonal tile only) ----
        if (jt == qt) {
            #pragma unroll
            for (int nt = 0; nt < 8; nt++) {
                #pragma unroll
                for (int f = 0; f < 4; f++) {
                    int kloc = nt * 8 + 2 * qcol + (f & 1);
                    int qloc = w16 + qrow + ((f >> 1) * 8);
                    if (kloc > qloc) c[nt][f] = -INFINITY;
                }
            }
        }

        // ---- online softmax ----
        float tl = -INFINITY, th = -INFINITY;
        #pragma unroll
        for (int nt = 0; nt < 8; nt++) {
            tl = fmaxf(tl, fmaxf(c[nt][0], c[nt][1]));
            th = fmaxf(th, fmaxf(c[nt][2], c[nt][3]));
        }
        tl = fmaxf(tl, __shfl_xor_sync(FULL, tl, 1, 4));
        tl = fmaxf(tl, __shfl_xor_sync(FULL, tl, 2, 4));
        th = fmaxf(th, __shfl_xor_sync(FULL, th, 1, 4));
        th = fmaxf(th, __shfl_xor_sync(FULL, th, 2, 4));

        float mn_lo = fmaxf(m_lo, tl);
        float mn_hi = fmaxf(m_hi, th);
        float f_lo = __expf(m_lo - mn_lo);
        float f_hi = __expf(m_hi - mn_hi);

        float rs_lo = 0.f, rs_hi = 0.f;
        #pragma unroll
        for (int nt = 0; nt < 8; nt++) {
            float p0 = __expf(c[nt][0] - mn_lo);
            float p1 = __expf(c[nt][1] - mn_lo);
            float p2 = __expf(c[nt][2] - mn_hi);
            float p3 = __expf(c[nt][3] - mn_hi);
            rs_lo += p0 + p1;
            rs_hi += p2 + p3;
            int col = nt * 8 + 2 * qcol;
            *(uint32_t*)&Ps[(w16 + qrow) * FP + col]     = pack_h2(p0, p1);
            *(uint32_t*)&Ps[(w16 + qrow + 8) * FP + col] = pack_h2(p2, p3);
        }
        rs_lo += __shfl_xor_sync(FULL, rs_lo, 1, 4);
        rs_lo += __shfl_xor_sync(FULL, rs_lo, 2, 4);
        rs_hi += __shfl_xor_sync(FULL, rs_hi, 1, 4);
        rs_hi += __shfl_xor_sync(FULL, rs_hi, 2, 4);

        l_lo = l_lo * f_lo + rs_lo;
        l_hi = l_hi * f_hi + rs_hi;
        m_lo = mn_lo;
        m_hi = mn_hi;
        #pragma unroll
        for (int nt = 0; nt < 8; nt++) {
            o[nt][0] *= f_lo; o[nt][1] *= f_lo;
            o[nt][2] *= f_hi; o[nt][3] *= f_hi;
        }
        __syncthreads();   // Ps complete

        // ---- O += P V ----
        #pragma unroll
        for (int ks = 0; ks < 4; ks++) {
            const __half* p0 = &Ps[(w16 + qrow) * FP + ks * 16 + 2 * qcol];
            const __half* p1 = &Ps[(w16 + qrow + 8) * FP + ks * 16 + 2 * qcol];
            uint32_t a0 = *(const uint32_t*)p0;
            uint32_t a1 = *(const uint32_t*)p1;
            uint32_t a2 = *(const uint32_t*)(p0 + 8);
            uint32_t a3 = *(const uint32_t*)(p1 + 8);
            #pragma unroll
            for (int nt = 0; nt < 8; nt++) {
                const __half* bp = &Vt[(nt * 8 + qrow) * FP + ks * 16 + 2 * qcol];
                mma_fp16(o[nt][0], o[nt][1], o[nt][2], o[nt][3],
                         a0, a1, a2, a3,
                         *(const uint32_t*)bp, *(const uint32_t*)(bp + 8));
            }
        }
    }

    // ---- epilogue: write (B,T,H,D) ----
    const float inv_lo = 1.f / l_lo;
    const float inv_hi = 1.f / l_hi;
    const int b = bh >> 4;
    const int h = bh & (HEADS - 1);
    const int row_lo = q0 + w16 + qrow;
    const int row_hi = row_lo + 8;
    #pragma unroll
    for (int nt = 0; nt < 8; nt++) {
        const int d = nt * 8 + 2 * qcol;
        *(float2*)&O[(((size_t)b * SEQ + row_lo) * HEADS + h) * HDIM + d] =
            make_float2(o[nt][0] * inv_lo, o[nt][1] * inv_lo);
        *(float2*)&O[(((size_t)b * SEQ + row_hi) * HEADS + h) * HDIM + d] =
            make_float2(o[nt][2] * inv_hi, o[nt][3] * inv_hi);
    }
}

// ---------------- launch -----------------------------------------------------
extern "C" void kernel_launch(void* const* d_in, const int* in_sizes, int n_in,
                              void* d_out, int out_size)
{
    const float* x  = (const float*)d_in[0];
    const float* Wq = (const float*)d_in[1];
    const float* Wk = (const float*)d_in[2];
    const float* Wv = (const float*)d_in[3];
    const float* Wo = (const float*)d_in[4];
    const float* bo = (const float*)d_in[5];
    float* out = (float*)d_out;

    float *Qp, *Kp, *Vp, *Ap;
    cudaGetSymbolAddress((void**)&Qp, g_Q);
    cudaGetSymbolAddress((void**)&Kp, g_K);
    cudaGetSymbolAddress((void**)&Vp, g_V);
    cudaGetSymbolAddress((void**)&Ap, g_AO);

    dim3 gg(EMB / GBN, MROWS / GBM);   // (8, 64)
    gemm_mma<<<gg, 256>>>(x, Wq, nullptr, Qp, MROWS, EMB, EMB, 0);
    gemm_mma<<<gg, 256>>>(x, Wk, nullptr, Kp, MROWS, EMB, EMB, 0);
    gemm_mma<<<gg, 256>>>(x, Wv, nullptr, Vp, MROWS, EMB, EMB, 0);

    flash_mma<<<dim3(SEQ / 64, BATCH * HEADS), 128>>>(Qp, Kp, Vp, Ap);

    gemm_mma<<<gg, 256>>>(Ap, Wo, bo, out, MROWS, EMB, EMB, 1);
}

// round 6
// speedup vs baseline: 1.6996x; 1.6996x over previous
#include <cuda_runtime.h>
#include <cuda_bf16.h>
#include <cuda_fp16.h>
#include <math.h>
#include <cstdint>

// Problem constants
#define BATCH 2
#define SEQ   4096
#define EMB   1024
#define HEADS 16
#define HDIM  64
#define MROWS (BATCH*SEQ)   // 8192

// ---------------- scratch (static device globals; no runtime allocation) ----
__device__ float g_Q[(size_t)BATCH*HEADS*SEQ*HDIM];   // (B,H,T,D)
__device__ float g_K[(size_t)BATCH*HEADS*SEQ*HDIM];
__device__ float g_V[(size_t)BATCH*HEADS*SEQ*HDIM];
__device__ float g_AO[(size_t)BATCH*SEQ*EMB];         // (B,T,E) attention output

__device__ __forceinline__ uint32_t f2tf32(float f) {
    uint32_t r;
    asm("cvt.rna.tf32.f32 %0, %1;" : "=r"(r) : "f"(f));
    return r;
}

__device__ __forceinline__ uint32_t pack_h2(float a, float b) {
    __half2 h = __floats2half2_rn(a, b);
    return *(uint32_t*)&h;
}

__device__ __forceinline__ void mma_tf32(
    float& c0, float& c1, float& c2, float& c3,
    uint32_t a0, uint32_t a1, uint32_t a2, uint32_t a3,
    uint32_t b0, uint32_t b1)
{
    asm volatile(
        "mma.sync.aligned.m16n8k8.row.col.f32.tf32.tf32.f32 "
        "{%0,%1,%2,%3}, {%4,%5,%6,%7}, {%8,%9}, {%0,%1,%2,%3};"
        : "+f"(c0), "+f"(c1), "+f"(c2), "+f"(c3)
        : "r"(a0), "r"(a1), "r"(a2), "r"(a3), "r"(b0), "r"(b1));
}

__device__ __forceinline__ void mma_fp16(
    float& c0, float& c1, float& c2, float& c3,
    uint32_t a0, uint32_t a1, uint32_t a2, uint32_t a3,
    uint32_t b0, uint32_t b1)
{
    asm volatile(
        "mma.sync.aligned.m16n8k16.row.col.f32.f16.f16.f32 "
        "{%0,%1,%2,%3}, {%4,%5,%6,%7}, {%8,%9}, {%0,%1,%2,%3};"
        : "+f"(c0), "+f"(c1), "+f"(c2), "+f"(c3)
        : "r"(a0), "r"(a1), "r"(a2), "r"(a3), "r"(b0), "r"(b1));
}

// ============================================================================
// tf32 mma.sync GEMM (proven; unchanged):
// C[m][n] = sum_k A[m][k] * W[n][k]  (+bias)
// ============================================================================
#define GBM 128
#define GBN 128
#define GBK 32
#define GPAD 36

__global__ __launch_bounds__(256) void gemm_mma(
    const float* __restrict__ A, const float* __restrict__ W,
    const float* __restrict__ bias, float* __restrict__ out,
    int M, int N, int K, int mode)
{
    __shared__ uint32_t As[GBM * GPAD];
    __shared__ uint32_t Bs[GBN * GPAD];

    const int tid = threadIdx.x;
    const int wid = tid >> 5;
    const int lid = tid & 31;
    const int qrow = lid >> 2;
    const int qcol = lid & 3;

    const int row0 = blockIdx.y * GBM;
    const int col0 = blockIdx.x * GBN;
    const int wm0 = (wid & 1) * 64;
    const int wn0 = (wid >> 1) * 32;

    float c[4][4][4];
    #pragma unroll
    for (int i = 0; i < 4; i++)
        #pragma unroll
        for (int j = 0; j < 4; j++)
            #pragma unroll
            for (int f = 0; f < 4; f++) c[i][j][f] = 0.f;

    for (int k0 = 0; k0 < K; k0 += GBK) {
        #pragma unroll
        for (int l = 0; l < 4; l++) {
            int idx = tid + l * 256;
            int r   = idx >> 3;
            int c4  = (idx & 7) * 4;
            float4 va = *(const float4*)&A[(size_t)(row0 + r) * K + k0 + c4];
            *(uint4*)&As[r * GPAD + c4] =
                make_uint4(f2tf32(va.x), f2tf32(va.y), f2tf32(va.z), f2tf32(va.w));
            float4 vb = *(const float4*)&W[(size_t)(col0 + r) * K + k0 + c4];
            *(uint4*)&Bs[r * GPAD + c4] =
                make_uint4(f2tf32(vb.x), f2tf32(vb.y), f2tf32(vb.z), f2tf32(vb.w));
        }
        __syncthreads();

        #pragma unroll
        for (int kk = 0; kk < GBK / 8; kk++) {
            const int kb = kk * 8;
            uint32_t a[4][4], b[4][2];
            #pragma unroll
            for (int mi = 0; mi < 4; mi++) {
                const uint32_t* ap = &As[(wm0 + mi * 16 + qrow) * GPAD + kb + qcol];
                a[mi][0] = ap[0];
                a[mi][1] = ap[8 * GPAD];
                a[mi][2] = ap[4];
                a[mi][3] = ap[8 * GPAD + 4];
            }
            #pragma unroll
            for (int ni = 0; ni < 4; ni++) {
                const uint32_t* bp = &Bs[(wn0 + ni * 8 + qrow) * GPAD + kb + qcol];
                b[ni][0] = bp[0];
                b[ni][1] = bp[4];
            }
            #pragma unroll
            for (int mi = 0; mi < 4; mi++)
                #pragma unroll
                for (int ni = 0; ni < 4; ni++)
                    mma_tf32(c[mi][ni][0], c[mi][ni][1], c[mi][ni][2], c[mi][ni][3],
                             a[mi][0], a[mi][1], a[mi][2], a[mi][3],
                             b[ni][0], b[ni][1]);
        }
        __syncthreads();
    }

    #pragma unroll
    for (int mi = 0; mi < 4; mi++) {
        #pragma unroll
        for (int half = 0; half < 2; half++) {
            const int m = row0 + wm0 + mi * 16 + qrow + half * 8;
            const int bi = m >> 12;
            const int t  = m & (SEQ - 1);
            #pragma unroll
            for (int ni = 0; ni < 4; ni++) {
                const int n = col0 + wn0 + ni * 8 + qcol * 2;
                float v0 = c[mi][ni][half * 2 + 0];
                float v1 = c[mi][ni][half * 2 + 1];
                if (mode == 0) {
                    const int h = n >> 6;
                    const int d = n & (HDIM - 1);
                    *(float2*)&out[(((size_t)bi * HEADS + h) * SEQ + t) * HDIM + d] =
                        make_float2(v0, v1);
                } else {
                    float2 bb = *(const float2*)&bias[n];
                    *(float2*)&out[(size_t)m * N + n] = make_float2(v0 + bb.x, v1 + bb.y);
                }
            }
        }
    }
}

// ============================================================================
// Flash attention, fp16 m16n8k16, 8 warps / 256 threads, 128 q-rows per CTA.
// Two 64-row warp-groups (warps 0-3 / 4-7) share one K/V tile per iteration.
// Ks: [key][d] halves (pad 72). Vt: [d][key] halves (pad 72), written via
// key-pair-packed half2 stores (banks 0..31, conflict-free).
// Ps[g]: [q][key] halves, warp-private (also Q staging).
// ============================================================================
#define FP  72   // halves per row
#define FPW 36   // words per row

__global__ __launch_bounds__(256) void flash_mma(
    const float* __restrict__ Q, const float* __restrict__ K,
    const float* __restrict__ V, float* __restrict__ O)
{
    __shared__ __half Ks[64 * FP];
    __shared__ __half Vt[64 * FP];
    __shared__ __half Ps[2][64 * FP];

    const int qt = blockIdx.x;             // 128-row q tile
    const int bh = blockIdx.y;
    const size_t base = (size_t)bh * SEQ * HDIM;
    const float* Qb = Q + base;
    const float* Kb = K + base;
    const float* Vb = V + base;

    const int tid  = threadIdx.x;
    const int wid  = tid >> 5;
    const int grp  = wid >> 2;             // warp-group 0/1
    const int w16  = (wid & 3) * 16;
    const int lid  = tid & 31;
    const int qrow = lid >> 2;
    const int qcol = lid & 3;
    const int q0   = qt * 128;
    const int jtmax = 2 * qt + grp;        // last K tile this group needs
    const unsigned FULL = 0xffffffffu;

    // ---- stage scaled Q (128 rows) into Ps[0..1], pull fragments ----
    #pragma unroll
    for (int l = 0; l < 8; l++) {
        int idx = tid + l * 256;           // 0..2047
        int r   = idx >> 4;                // 0..127
        int d4  = (idx & 15) * 4;
        float4 v = *(const float4*)&Qb[(size_t)(q0 + r) * HDIM + d4];
        *(uint2*)&Ps[r >> 6][(r & 63) * FP + d4] =
            make_uint2(pack_h2(v.x * 0.125f, v.y * 0.125f),
                       pack_h2(v.z * 0.125f, v.w * 0.125f));
    }
    __syncthreads();

    uint32_t aq[4][4];
    #pragma unroll
    for (int ks = 0; ks < 4; ks++) {
        const __half* p0 = &Ps[grp][(w16 + qrow) * FP + ks * 16 + 2 * qcol];
        const __half* p1 = &Ps[grp][(w16 + qrow + 8) * FP + ks * 16 + 2 * qcol];
        aq[ks][0] = *(const uint32_t*)p0;
        aq[ks][1] = *(const uint32_t*)p1;
        aq[ks][2] = *(const uint32_t*)(p0 + 8);
        aq[ks][3] = *(const uint32_t*)(p1 + 8);
    }

    float o[8][4];
    #pragma unroll
    for (int nt = 0; nt < 8; nt++)
        #pragma unroll
        for (int f = 0; f < 4; f++) o[nt][f] = 0.f;
    float m_lo = -INFINITY, m_hi = -INFINITY, l_lo = 0.f, l_hi = 0.f;

    for (int jt = 0; jt <= 2 * qt + 1; jt++) {
        __syncthreads();   // everyone done with Ks/Vt (and Q staging on iter 0)

        // ---- fill K [key][d]: 4 iters, 16B loads, 8B conflict-free stores ----
        #pragma unroll
        for (int l = 0; l < 4; l++) {
            int idx = tid + l * 256;       // 0..1023
            int r   = idx >> 4;            // 0..63
            int d4  = (idx & 15) * 4;
            float4 kv = *(const float4*)&Kb[(size_t)(jt * 64 + r) * HDIM + d4];
            *(uint2*)&Ks[r * FP + d4] =
                make_uint2(pack_h2(kv.x, kv.y), pack_h2(kv.z, kv.w));
        }
        // ---- fill Vt [d][key]: key-pair packed half2 stores, banks 0..31 ----
        #pragma unroll
        for (int l = 0; l < 2; l++) {
            int task = tid + l * 256;      // 0..511
            int kp   = task & 31;          // key pair
            int d4   = (task >> 5) * 4;    // 0..60
            const float* va = &Vb[(size_t)(jt * 64 + 2 * kp) * HDIM + d4];
            float4 v0 = *(const float4*)va;
            float4 v1 = *(const float4*)(va + HDIM);
            uint32_t* dst = (uint32_t*)Vt;
            dst[(d4 + 0) * FPW + kp] = pack_h2(v0.x, v1.x);
            dst[(d4 + 1) * FPW + kp] = pack_h2(v0.y, v1.y);
            dst[(d4 + 2) * FPW + kp] = pack_h2(v0.z, v1.z);
            dst[(d4 + 3) * FPW + kp] = pack_h2(v0.w, v1.w);
        }
        __syncthreads();

        if (jt > jtmax) continue;          // group 0 skips the last odd tile

        // ---- S = Q K^T ----
        float c[8][4];
        #pragma unroll
        for (int nt = 0; nt < 8; nt++)
            #pragma unroll
            for (int f = 0; f < 4; f++) c[nt][f] = 0.f;

        #pragma unroll
        for (int ks = 0; ks < 4; ks++) {
            #pragma unroll
            for (int nt = 0; nt < 8; nt++) {
                const __half* bp = &Ks[(nt * 8 + qrow) * FP + ks * 16 + 2 * qcol];
                mma_fp16(c[nt][0], c[nt][1], c[nt][2], c[nt][3],
                         aq[ks][0], aq[ks][1], aq[ks][2], aq[ks][3],
                         *(const uint32_t*)bp, *(const uint32_t*)(bp + 8));
            }
        }

        // ---- causal mask (diagonal tile of this group) ----
        if (jt == jtmax) {
            #pragma unroll
            for (int nt = 0; nt < 8; nt++) {
                #pragma unroll
                for (int f = 0; f < 4; f++) {
                    int kloc = nt * 8 + 2 * qcol + (f & 1);
                    int qloc = w16 + qrow + ((f >> 1) * 8);
                    if (kloc > qloc) c[nt][f] = -INFINITY;
                }
            }
        }

        // ---- online softmax ----
        float tl = -INFINITY, th = -INFINITY;
        #pragma unroll
        for (int nt = 0; nt < 8; nt++) {
            tl = fmaxf(tl, fmaxf(c[nt][0], c[nt][1]));
            th = fmaxf(th, fmaxf(c[nt][2], c[nt][3]));
        }
        tl = fmaxf(tl, __shfl_xor_sync(FULL, tl, 1, 4));
        tl = fmaxf(tl, __shfl_xor_sync(FULL, tl, 2, 4));
        th = fmaxf(th, __shfl_xor_sync(FULL, th, 1, 4));
        th = fmaxf(th, __shfl_xor_sync(FULL, th, 2, 4));

        float mn_lo = fmaxf(m_lo, tl);
        float mn_hi = fmaxf(m_hi, th);
        float f_lo = __expf(m_lo - mn_lo);
        float f_hi = __expf(m_hi - mn_hi);

        float rs_lo = 0.f, rs_hi = 0.f;
        #pragma unroll
        for (int nt = 0; nt < 8; nt++) {
            float p0 = __expf(c[nt][0] - mn_lo);
            float p1 = __expf(c[nt][1] - mn_lo);
            float p2 = __expf(c[nt][2] - mn_hi);
            float p3 = __expf(c[nt][3] - mn_hi);
            rs_lo += p0 + p1;
            rs_hi += p2 + p3;
            int col = nt * 8 + 2 * qcol;
            *(uint32_t*)&Ps[grp][(w16 + qrow) * FP + col]     = pack_h2(p0, p1);
            *(uint32_t*)&Ps[grp][(w16 + qrow + 8) * FP + col] = pack_h2(p2, p3);
        }
        rs_lo += __shfl_xor_sync(FULL, rs_lo, 1, 4);
        rs_lo += __shfl_xor_sync(FULL, rs_lo, 2, 4);
        rs_hi += __shfl_xor_sync(FULL, rs_hi, 1, 4);
        rs_hi += __shfl_xor_sync(FULL, rs_hi, 2, 4);

        l_lo = l_lo * f_lo + rs_lo;
        l_hi = l_hi * f_hi + rs_hi;
        m_lo = mn_lo;
        m_hi = mn_hi;
        #pragma unroll
        for (int nt = 0; nt < 8; nt++) {
            o[nt][0] *= f_lo; o[nt][1] *= f_lo;
            o[nt][2] *= f_hi; o[nt][3] *= f_hi;
        }
        __syncwarp();      // Ps rows are warp-private; order write -> read

        // ---- O += P V ----
        #pragma unroll
        for (int ks = 0; ks < 4; ks++) {
            const __half* p0 = &Ps[grp][(w16 + qrow) * FP + ks * 16 + 2 * qcol];
            const __half* p1 = &Ps[grp][(w16 + qrow + 8) * FP + ks * 16 + 2 * qcol];
            uint32_t a0 = *(const uint32_t*)p0;
            uint32_t a1 = *(const uint32_t*)p1;
            uint32_t a2 = *(const uint32_t*)(p0 + 8);
            uint32_t a3 = *(const uint32_t*)(p1 + 8);
            #pragma unroll
            for (int nt = 0; nt < 8; nt++) {
                const __half* bp = &Vt[(nt * 8 + qrow) * FP + ks * 16 + 2 * qcol];
                mma_fp16(o[nt][0], o[nt][1], o[nt][2], o[nt][3],
                         a0, a1, a2, a3,
                         *(const uint32_t*)bp, *(const uint32_t*)(bp + 8));
            }
        }
    }

    // ---- epilogue: write (B,T,H,D) ----
    const float inv_lo = 1.f / l_lo;
    const float inv_hi = 1.f / l_hi;
    const int b = bh >> 4;
    const int h = bh & (HEADS - 1);
    const int row_lo = q0 + grp * 64 + w16 + qrow;
    const int row_hi = row_lo + 8;
    #pragma unroll
    for (int nt = 0; nt < 8; nt++) {
        const int d = nt * 8 + 2 * qcol;
        *(float2*)&O[(((size_t)b * SEQ + row_lo) * HEADS + h) * HDIM + d] =
            make_float2(o[nt][0] * inv_lo, o[nt][1] * inv_lo);
        *(float2*)&O[(((size_t)b * SEQ + row_hi) * HEADS + h) * HDIM + d] =
            make_float2(o[nt][2] * inv_hi, o[nt][3] * inv_hi);
    }
}

// ---------------- launch -----------------------------------------------------
extern "C" void kernel_launch(void* const* d_in, const int* in_sizes, int n_in,
                              void* d_out, int out_size)
{
    const float* x  = (const float*)d_in[0];
    const float* Wq = (const float*)d_in[1];
    const float* Wk = (const float*)d_in[2];
    const float* Wv = (const float*)d_in[3];
    const float* Wo = (const float*)d_in[4];
    const float* bo = (const float*)d_in[5];
    float* out = (float*)d_out;

    float *Qp, *Kp, *Vp, *Ap;
    cudaGetSymbolAddress((void**)&Qp, g_Q);
    cudaGetSymbolAddress((void**)&Kp, g_K);
    cudaGetSymbolAddress((void**)&Vp, g_V);
    cudaGetSymbolAddress((void**)&Ap, g_AO);

    dim3 gg(EMB / GBN, MROWS / GBM);   // (8, 64)
    gemm_mma<<<gg, 256>>>(x, Wq, nullptr, Qp, MROWS, EMB, EMB, 0);
    gemm_mma<<<gg, 256>>>(x, Wk, nullptr, Kp, MROWS, EMB, EMB, 0);
    gemm_mma<<<gg, 256>>>(x, Wv, nullptr, Vp, MROWS, EMB, EMB, 0);

    flash_mma<<<dim3(SEQ / 128, BATCH * HEADS), 256>>>(Qp, Kp, Vp, Ap);

    gemm_mma<<<gg, 256>>>(Ap, Wo, bo, out, MROWS, EMB, EMB, 1);
}

// round 7
// speedup vs baseline: 2.5860x; 1.5216x over previous
#include <cuda_runtime.h>
#include <cuda_bf16.h>
#include <cuda_fp16.h>
#include <math.h>
#include <cstdint>

// Problem constants
#define BATCH 2
#define SEQ   4096
#define EMB   1024
#define HEADS 16
#define HDIM  64
#define MROWS (BATCH*SEQ)   // 8192

// ---------------- scratch (static device globals; no runtime allocation) ----
__device__ __half g_Qh[(size_t)BATCH*HEADS*SEQ*HDIM];  // (B,H,T,D), pre-scaled 1/8
__device__ __half g_Kh[(size_t)BATCH*HEADS*SEQ*HDIM];
__device__ __half g_Vh[(size_t)BATCH*HEADS*SEQ*HDIM];
__device__ __half g_AOh[(size_t)BATCH*SEQ*EMB];        // (B,T,E)

__device__ __forceinline__ uint32_t pack_h2(float a, float b) {
    __half2 h = __floats2half2_rn(a, b);
    return *(uint32_t*)&h;
}

__device__ __forceinline__ uint32_t cvta_smem(const void* p) {
    uint32_t a;
    asm("{ .reg .u64 t; cvta.to.shared.u64 t, %1; cvt.u32.u64 %0, t; }"
        : "=r"(a) : "l"(p));
    return a;
}

__device__ __forceinline__ void ldm_x4(
    uint32_t& r0, uint32_t& r1, uint32_t& r2, uint32_t& r3, uint32_t addr)
{
    asm volatile("ldmatrix.sync.aligned.m8n8.x4.shared.b16 {%0,%1,%2,%3}, [%4];"
        : "=r"(r0), "=r"(r1), "=r"(r2), "=r"(r3) : "r"(addr));
}

__device__ __forceinline__ void ldm_x4_t(
    uint32_t& r0, uint32_t& r1, uint32_t& r2, uint32_t& r3, uint32_t addr)
{
    asm volatile("ldmatrix.sync.aligned.m8n8.x4.trans.shared.b16 {%0,%1,%2,%3}, [%4];"
        : "=r"(r0), "=r"(r1), "=r"(r2), "=r"(r3) : "r"(addr));
}

__device__ __forceinline__ void mma_fp16(
    float& c0, float& c1, float& c2, float& c3,
    uint32_t a0, uint32_t a1, uint32_t a2, uint32_t a3,
    uint32_t b0, uint32_t b1)
{
    asm volatile(
        "mma.sync.aligned.m16n8k16.row.col.f32.f16.f16.f32 "
        "{%0,%1,%2,%3}, {%4,%5,%6,%7}, {%8,%9}, {%0,%1,%2,%3};"
        : "+f"(c0), "+f"(c1), "+f"(c2), "+f"(c3)
        : "r"(a0), "r"(a1), "r"(a2), "r"(a3), "r"(b0), "r"(b1));
}

// ============================================================================
// fp16 m16n8k16 GEMM: C[m][n] = sum_k A[m][k]*W[n][k]
// CTA 128x128x32, 256 threads, warp tile 64x32 (proven addressing pattern).
// gemm_proj: A fp32, out half scattered to (B,H,T,D), scaled.
// gemm_final: A half, out fp32 row-major + bias.
// ============================================================================
#define GPH 40   // halves per smem row (80 B) — conflict-free frag loads

__global__ __launch_bounds__(256) void gemm_proj(
    const float* __restrict__ A, const float* __restrict__ W,
    __half* __restrict__ out, float scale)
{
    __shared__ __half As[128 * GPH];
    __shared__ __half Bs[128 * GPH];

    const int tid = threadIdx.x;
    const int wid = tid >> 5;
    const int lid = tid & 31;
    const int qrow = lid >> 2;
    const int qcol = lid & 3;
    const int row0 = blockIdx.y * 128;
    const int col0 = blockIdx.x * 128;
    const int wm0 = (wid & 1) * 64;
    const int wn0 = (wid >> 1) * 32;

    float c[4][4][4];
    #pragma unroll
    for (int i = 0; i < 4; i++)
        #pragma unroll
        for (int j = 0; j < 4; j++)
            #pragma unroll
            for (int f = 0; f < 4; f++) c[i][j][f] = 0.f;

    for (int k0 = 0; k0 < EMB; k0 += 32) {
        #pragma unroll
        for (int l = 0; l < 4; l++) {
            int idx = tid + l * 256;     // 0..1023
            int r   = idx >> 3;
            int c4  = (idx & 7) * 4;
            float4 va = *(const float4*)&A[(size_t)(row0 + r) * EMB + k0 + c4];
            *(uint2*)&As[r * GPH + c4] =
                make_uint2(pack_h2(va.x, va.y), pack_h2(va.z, va.w));
            float4 vb = *(const float4*)&W[(size_t)(col0 + r) * EMB + k0 + c4];
            *(uint2*)&Bs[r * GPH + c4] =
                make_uint2(pack_h2(vb.x, vb.y), pack_h2(vb.z, vb.w));
        }
        __syncthreads();

        #pragma unroll
        for (int ks = 0; ks < 2; ks++) {
            const int kb = ks * 16 + 2 * qcol;
            uint32_t a[4][4], b[4][2];
            #pragma unroll
            for (int mi = 0; mi < 4; mi++) {
                const __half* ap = &As[(wm0 + mi * 16 + qrow) * GPH + kb];
                a[mi][0] = *(const uint32_t*)ap;
                a[mi][1] = *(const uint32_t*)(ap + 8 * GPH);
                a[mi][2] = *(const uint32_t*)(ap + 8);
                a[mi][3] = *(const uint32_t*)(ap + 8 * GPH + 8);
            }
            #pragma unroll
            for (int ni = 0; ni < 4; ni++) {
                const __half* bp = &Bs[(wn0 + ni * 8 + qrow) * GPH + kb];
                b[ni][0] = *(const uint32_t*)bp;
                b[ni][1] = *(const uint32_t*)(bp + 8);
            }
            #pragma unroll
            for (int mi = 0; mi < 4; mi++)
                #pragma unroll
                for (int ni = 0; ni < 4; ni++)
                    mma_fp16(c[mi][ni][0], c[mi][ni][1], c[mi][ni][2], c[mi][ni][3],
                             a[mi][0], a[mi][1], a[mi][2], a[mi][3],
                             b[ni][0], b[ni][1]);
        }
        __syncthreads();
    }

    // scatter to (B,H,T,D) as half, scaled
    #pragma unroll
    for (int mi = 0; mi < 4; mi++) {
        #pragma unroll
        for (int half_ = 0; half_ < 2; half_++) {
            const int m = row0 + wm0 + mi * 16 + qrow + half_ * 8;
            const int bi = m >> 12;
            const int t  = m & (SEQ - 1);
            #pragma unroll
            for (int ni = 0; ni < 4; ni++) {
                const int n = col0 + wn0 + ni * 8 + qcol * 2;
                const int h = n >> 6;
                const int d = n & (HDIM - 1);
                *(uint32_t*)&out[(((size_t)bi * HEADS + h) * SEQ + t) * HDIM + d] =
                    pack_h2(c[mi][ni][half_ * 2] * scale, c[mi][ni][half_ * 2 + 1] * scale);
            }
        }
    }
}

__global__ __launch_bounds__(256) void gemm_final(
    const __half* __restrict__ A, const float* __restrict__ W,
    const float* __restrict__ bias, float* __restrict__ out)
{
    __shared__ __half As[128 * GPH];
    __shared__ __half Bs[128 * GPH];

    const int tid = threadIdx.x;
    const int wid = tid >> 5;
    const int lid = tid & 31;
    const int qrow = lid >> 2;
    const int qcol = lid & 3;
    const int row0 = blockIdx.y * 128;
    const int col0 = blockIdx.x * 128;
    const int wm0 = (wid & 1) * 64;
    const int wn0 = (wid >> 1) * 32;

    float c[4][4][4];
    #pragma unroll
    for (int i = 0; i < 4; i++)
        #pragma unroll
        for (int j = 0; j < 4; j++)
            #pragma unroll
            for (int f = 0; f < 4; f++) c[i][j][f] = 0.f;

    for (int k0 = 0; k0 < EMB; k0 += 32) {
        #pragma unroll
        for (int l = 0; l < 2; l++) {      // A: 512 uint4 copies
            int idx = tid + l * 256;
            int r   = idx >> 2;
            int c8  = (idx & 3) * 8;
            *(uint4*)&As[r * GPH + c8] =
                *(const uint4*)&A[(size_t)(row0 + r) * EMB + k0 + c8];
        }
        #pragma unroll
        for (int l = 0; l < 4; l++) {      // W: fp32 -> half
            int idx = tid + l * 256;
            int r   = idx >> 3;
            int c4  = (idx & 7) * 4;
            float4 vb = *(const float4*)&W[(size_t)(col0 + r) * EMB + k0 + c4];
            *(uint2*)&Bs[r * GPH + c4] =
                make_uint2(pack_h2(vb.x, vb.y), pack_h2(vb.z, vb.w));
        }
        __syncthreads();

        #pragma unroll
        for (int ks = 0; ks < 2; ks++) {
            const int kb = ks * 16 + 2 * qcol;
            uint32_t a[4][4], b[4][2];
            #pragma unroll
            for (int mi = 0; mi < 4; mi++) {
                const __half* ap = &As[(wm0 + mi * 16 + qrow) * GPH + kb];
                a[mi][0] = *(const uint32_t*)ap;
                a[mi][1] = *(const uint32_t*)(ap + 8 * GPH);
                a[mi][2] = *(const uint32_t*)(ap + 8);
                a[mi][3] = *(const uint32_t*)(ap + 8 * GPH + 8);
            }
            #pragma unroll
            for (int ni = 0; ni < 4; ni++) {
                const __half* bp = &Bs[(wn0 + ni * 8 + qrow) * GPH + kb];
                b[ni][0] = *(const uint32_t*)bp;
                b[ni][1] = *(const uint32_t*)(bp + 8);
            }
            #pragma unroll
            for (int mi = 0; mi < 4; mi++)
                #pragma unroll
                for (int ni = 0; ni < 4; ni++)
                    mma_fp16(c[mi][ni][0], c[mi][ni][1], c[mi][ni][2], c[mi][ni][3],
                             a[mi][0], a[mi][1], a[mi][2], a[mi][3],
                             b[ni][0], b[ni][1]);
        }
        __syncthreads();
    }

    #pragma unroll
    for (int mi = 0; mi < 4; mi++) {
        #pragma unroll
        for (int half_ = 0; half_ < 2; half_++) {
            const int m = row0 + wm0 + mi * 16 + qrow + half_ * 8;
            #pragma unroll
            for (int ni = 0; ni < 4; ni++) {
                const int n = col0 + wn0 + ni * 8 + qcol * 2;
                float2 bb = *(const float2*)&bias[n];
                *(float2*)&out[(size_t)m * EMB + n] =
                    make_float2(c[mi][ni][half_ * 2] + bb.x,
                                c[mi][ni][half_ * 2 + 1] + bb.y);
            }
        }
    }
}

// ============================================================================
// Flash attention, fp16 in/out, ldmatrix fragments.
// 8 warps / 256 threads, 128 q-rows per CTA (two 64-row groups share K/V).
// Ks,Vs: [key][d] halves, pad 72. Ps[g]: [q][key] (also Q staging).
// ============================================================================
#define FP  72

__global__ __launch_bounds__(256) void flash_mma(
    const __half* __restrict__ Q, const __half* __restrict__ K,
    const __half* __restrict__ V, __half* __restrict__ O)
{
    __shared__ __half Ks[64 * FP];
    __shared__ __half Vs[64 * FP];
    __shared__ __half Ps[2][64 * FP];

    const int qt = blockIdx.x;
    const int bh = blockIdx.y;
    const size_t base = (size_t)bh * SEQ * HDIM;
    const __half* Qb = Q + base;
    const __half* Kb = K + base;
    const __half* Vb = V + base;

    const int tid  = threadIdx.x;
    const int wid  = tid >> 5;
    const int grp  = wid >> 2;
    const int w16  = (wid & 3) * 16;
    const int lid  = tid & 31;
    const int qrow = lid >> 2;
    const int qcol = lid & 3;
    const int q0   = qt * 128;
    const int jtmax = 2 * qt + grp;
    const unsigned FULL = 0xffffffffu;

    // ldmatrix per-lane base addresses
    const int i8 = lid & 7;
    const int g1 = (lid >> 3) & 1;
    const int g2 = (lid >> 4) & 1;
    const uint32_t paddr = cvta_smem(&Ps[grp][0]) +
        (uint32_t)(((w16 + g1 * 8 + i8) * FP + g2 * 8) * 2);
    uint32_t kaddr[4], vaddr[4];
    {
        const uint32_t kb_ = cvta_smem(Ks);
        const uint32_t vb_ = cvta_smem(Vs);
        #pragma unroll
        for (int ntp = 0; ntp < 4; ntp++) {
            kaddr[ntp] = kb_ + (uint32_t)((((2 * ntp + g2) * 8 + i8) * FP + g1 * 8) * 2);
            vaddr[ntp] = vb_ + (uint32_t)(((g1 * 8 + i8) * FP + (2 * ntp + g2) * 8) * 2);
        }
    }

    // ---- stage Q (pre-scaled half) into Ps, pull A-fragments ----
    #pragma unroll
    for (int l = 0; l < 4; l++) {
        int idx = tid + l * 256;           // 0..1023 uint4 slots
        int r   = idx >> 3;                // 0..127
        int c8  = (idx & 7) * 8;
        *(uint4*)&Ps[r >> 6][(r & 63) * FP + c8] =
            *(const uint4*)&Qb[(size_t)(q0 + r) * HDIM + c8];
    }
    __syncthreads();

    uint32_t aq[4][4];
    #pragma unroll
    for (int ks = 0; ks < 4; ks++)
        ldm_x4(aq[ks][0], aq[ks][1], aq[ks][2], aq[ks][3], paddr + ks * 32);

    float o[8][4];
    #pragma unroll
    for (int nt = 0; nt < 8; nt++)
        #pragma unroll
        for (int f = 0; f < 4; f++) o[nt][f] = 0.f;
    float m_lo = -INFINITY, m_hi = -INFINITY, l_lo = 0.f, l_hi = 0.f;

    for (int jt = 0; jt <= 2 * qt + 1; jt++) {
        __syncthreads();
        // ---- fill K and V: plain 16B copies ----
        #pragma unroll
        for (int l = 0; l < 2; l++) {
            int idx = tid + l * 256;       // 0..511
            int r   = idx >> 3;            // 0..63
            int c8  = (idx & 7) * 8;
            size_t g = (size_t)(jt * 64 + r) * HDIM + c8;
            *(uint4*)&Ks[r * FP + c8] = *(const uint4*)&Kb[g];
            *(uint4*)&Vs[r * FP + c8] = *(const uint4*)&Vb[g];
        }
        __syncthreads();

        if (jt > jtmax) continue;

        // ---- S = Q K^T ----
        float c[8][4];
        #pragma unroll
        for (int nt = 0; nt < 8; nt++)
            #pragma unroll
            for (int f = 0; f < 4; f++) c[nt][f] = 0.f;

        #pragma unroll
        for (int ks = 0; ks < 4; ks++) {
            #pragma unroll
            for (int ntp = 0; ntp < 4; ntp++) {
                uint32_t b0, b1, b2, b3;
                ldm_x4(b0, b1, b2, b3, kaddr[ntp] + ks * 32);
                mma_fp16(c[2*ntp][0], c[2*ntp][1], c[2*ntp][2], c[2*ntp][3],
                         aq[ks][0], aq[ks][1], aq[ks][2], aq[ks][3], b0, b1);
                mma_fp16(c[2*ntp+1][0], c[2*ntp+1][1], c[2*ntp+1][2], c[2*ntp+1][3],
                         aq[ks][0], aq[ks][1], aq[ks][2], aq[ks][3], b2, b3);
            }
        }

        // ---- causal mask (diagonal tile of this group) ----
        if (jt == jtmax) {
            #pragma unroll
            for (int nt = 0; nt < 8; nt++) {
                #pragma unroll
                for (int f = 0; f < 4; f++) {
                    int kloc = nt * 8 + 2 * qcol + (f & 1);
                    int qloc = w16 + qrow + ((f >> 1) * 8);
                    if (kloc > qloc) c[nt][f] = -INFINITY;
                }
            }
        }

        // ---- online softmax ----
        float tl = -INFINITY, th = -INFINITY;
        #pragma unroll
        for (int nt = 0; nt < 8; nt++) {
            tl = fmaxf(tl, fmaxf(c[nt][0], c[nt][1]));
            th = fmaxf(th, fmaxf(c[nt][2], c[nt][3]));
        }
        tl = fmaxf(tl, __shfl_xor_sync(FULL, tl, 1, 4));
        tl = fmaxf(tl, __shfl_xor_sync(FULL, tl, 2, 4));
        th = fmaxf(th, __shfl_xor_sync(FULL, th, 1, 4));
        th = fmaxf(th, __shfl_xor_sync(FULL, th, 2, 4));

        float mn_lo = fmaxf(m_lo, tl);
        float mn_hi = fmaxf(m_hi, th);
        float f_lo = __expf(m_lo - mn_lo);
        float f_hi = __expf(m_hi - mn_hi);

        float rs_lo = 0.f, rs_hi = 0.f;
        #pragma unroll
        for (int nt = 0; nt < 8; nt++) {
            float p0 = __expf(c[nt][0] - mn_lo);
            float p1 = __expf(c[nt][1] - mn_lo);
            float p2 = __expf(c[nt][2] - mn_hi);
            float p3 = __expf(c[nt][3] - mn_hi);
            rs_lo += p0 + p1;
            rs_hi += p2 + p3;
            int col = nt * 8 + 2 * qcol;
            *(uint32_t*)&Ps[grp][(w16 + qrow) * FP + col]     = pack_h2(p0, p1);
            *(uint32_t*)&Ps[grp][(w16 + qrow + 8) * FP + col] = pack_h2(p2, p3);
        }
        rs_lo += __shfl_xor_sync(FULL, rs_lo, 1, 4);
        rs_lo += __shfl_xor_sync(FULL, rs_lo, 2, 4);
        rs_hi += __shfl_xor_sync(FULL, rs_hi, 1, 4);
        rs_hi += __shfl_xor_sync(FULL, rs_hi, 2, 4);

        l_lo = l_lo * f_lo + rs_lo;
        l_hi = l_hi * f_hi + rs_hi;
        m_lo = mn_lo;
        m_hi = mn_hi;
        #pragma unroll
        for (int nt = 0; nt < 8; nt++) {
            o[nt][0] *= f_lo; o[nt][1] *= f_lo;
            o[nt][2] *= f_hi; o[nt][3] *= f_hi;
        }
        __syncwarp();      // Ps rows warp-private: order STS -> ldmatrix

        // ---- O += P V (V row-major, trans ldmatrix B-fragments) ----
        #pragma unroll
        for (int ks = 0; ks < 4; ks++) {
            uint32_t a0, a1, a2, a3;
            ldm_x4(a0, a1, a2, a3, paddr + ks * 32);
            #pragma unroll
            for (int ntp = 0; ntp < 4; ntp++) {
                uint32_t v0, v1, v2, v3;
                ldm_x4_t(v0, v1, v2, v3, vaddr[ntp] + ks * (16 * FP * 2));
                mma_fp16(o[2*ntp][0], o[2*ntp][1], o[2*ntp][2], o[2*ntp][3],
                         a0, a1, a2, a3, v0, v1);
                mma_fp16(o[2*ntp+1][0], o[2*ntp+1][1], o[2*ntp+1][2], o[2*ntp+1][3],
                         a0, a1, a2, a3, v2, v3);
            }
        }
    }

    // ---- epilogue: write half (B,T,E) ----
    const float inv_lo = 1.f / l_lo;
    const float inv_hi = 1.f / l_hi;
    const int b = bh >> 4;
    const int h = bh & (HEADS - 1);
    const int row_lo = q0 + grp * 64 + w16 + qrow;
    const int row_hi = row_lo + 8;
    #pragma unroll
    for (int nt = 0; nt < 8; nt++) {
        const int e = h * HDIM + nt * 8 + 2 * qcol;
        *(uint32_t*)&O[((size_t)(b * SEQ) + row_lo) * EMB + e] =
            pack_h2(o[nt][0] * inv_lo, o[nt][1] * inv_lo);
        *(uint32_t*)&O[((size_t)(b * SEQ) + row_hi) * EMB + e] =
            pack_h2(o[nt][2] * inv_hi, o[nt][3] * inv_hi);
    }
}

// ---------------- launch -----------------------------------------------------
extern "C" void kernel_launch(void* const* d_in, const int* in_sizes, int n_in,
                              void* d_out, int out_size)
{
    const float* x  = (const float*)d_in[0];
    const float* Wq = (const float*)d_in[1];
    const float* Wk = (const float*)d_in[2];
    const float* Wv = (const float*)d_in[3];
    const float* Wo = (const float*)d_in[4];
    const float* bo = (const float*)d_in[5];
    float* out = (float*)d_out;

    __half *Qp, *Kp, *Vp, *Ap;
    cudaGetSymbolAddress((void**)&Qp, g_Qh);
    cudaGetSymbolAddress((void**)&Kp, g_Kh);
    cudaGetSymbolAddress((void**)&Vp, g_Vh);
    cudaGetSymbolAddress((void**)&Ap, g_AOh);

    dim3 gg(EMB / 128, MROWS / 128);   // (8, 64)
    gemm_proj<<<gg, 256>>>(x, Wq, Qp, 0.125f);
    gemm_proj<<<gg, 256>>>(x, Wk, Kp, 1.0f);
    gemm_proj<<<gg, 256>>>(x, Wv, Vp, 1.0f);

    flash_mma<<<dim3(SEQ / 128, BATCH * HEADS), 256>>>(Qp, Kp, Vp, Ap);

    gemm_final<<<gg, 256>>>(Ap, Wo, bo, out);
}

// round 8
// speedup vs baseline: 2.8164x; 1.0891x over previous
#include <cuda_runtime.h>
#include <cuda_bf16.h>
#include <cuda_fp16.h>
#include <math.h>
#include <cstdint>

// Problem constants
#define BATCH 2
#define SEQ   4096
#define EMB   1024
#define HEADS 16
#define HDIM  64
#define MROWS (BATCH*SEQ)   // 8192

// ---------------- scratch (static device globals; no runtime allocation) ----
__device__ __half g_Qh[(size_t)BATCH*HEADS*SEQ*HDIM];  // (B,H,T,D), pre-scaled 1/8
__device__ __half g_Kh[(size_t)BATCH*HEADS*SEQ*HDIM];
__device__ __half g_Vh[(size_t)BATCH*HEADS*SEQ*HDIM];
__device__ __half g_AOh[(size_t)BATCH*SEQ*EMB];        // (B,T,E)
__device__ __half g_xh[(size_t)MROWS*EMB];
__device__ __half g_Wh[4][(size_t)EMB*EMB];            // Wq,Wk,Wv,Wo as half

__device__ __forceinline__ uint32_t pack_h2(float a, float b) {
    __half2 h = __floats2half2_rn(a, b);
    return *(uint32_t*)&h;
}

__device__ __forceinline__ uint32_t cvta_smem(const void* p) {
    uint32_t a;
    asm("{ .reg .u64 t; cvta.to.shared.u64 t, %1; cvt.u32.u64 %0, t; }"
        : "=r"(a) : "l"(p));
    return a;
}

__device__ __forceinline__ void cp16(uint32_t smem, const void* g) {
    asm volatile("cp.async.cg.shared.global [%0], [%1], 16;" :: "r"(smem), "l"(g));
}
#define CP_COMMIT() asm volatile("cp.async.commit_group;" ::: "memory")
#define CP_WAIT(n)  asm volatile("cp.async.wait_group %0;" :: "n"(n) : "memory")

__device__ __forceinline__ void ldm_x4(
    uint32_t& r0, uint32_t& r1, uint32_t& r2, uint32_t& r3, uint32_t addr)
{
    asm volatile("ldmatrix.sync.aligned.m8n8.x4.shared.b16 {%0,%1,%2,%3}, [%4];"
        : "=r"(r0), "=r"(r1), "=r"(r2), "=r"(r3) : "r"(addr));
}

__device__ __forceinline__ void ldm_x4_t(
    uint32_t& r0, uint32_t& r1, uint32_t& r2, uint32_t& r3, uint32_t addr)
{
    asm volatile("ldmatrix.sync.aligned.m8n8.x4.trans.shared.b16 {%0,%1,%2,%3}, [%4];"
        : "=r"(r0), "=r"(r1), "=r"(r2), "=r"(r3) : "r"(addr));
}

__device__ __forceinline__ void mma_fp16(
    float& c0, float& c1, float& c2, float& c3,
    uint32_t a0, uint32_t a1, uint32_t a2, uint32_t a3,
    uint32_t b0, uint32_t b1)
{
    asm volatile(
        "mma.sync.aligned.m16n8k16.row.col.f32.f16.f16.f32 "
        "{%0,%1,%2,%3}, {%4,%5,%6,%7}, {%8,%9}, {%0,%1,%2,%3};"
        : "+f"(c0), "+f"(c1), "+f"(c2), "+f"(c3)
        : "r"(a0), "r"(a1), "r"(a2), "r"(a3), "r"(b0), "r"(b1));
}

// ---------------- fp32 -> fp16 convert (8 elems/thread) ----------------------
__global__ __launch_bounds__(256) void f2h(
    const float* __restrict__ in, __half* __restrict__ out, int n)
{
    int i = (blockIdx.x * 256 + threadIdx.x) * 8;
    if (i >= n) return;
    float4 a = *(const float4*)&in[i];
    float4 b = *(const float4*)&in[i + 4];
    *(uint4*)&out[i] = make_uint4(pack_h2(a.x, a.y), pack_h2(a.z, a.w),
                                  pack_h2(b.x, b.y), pack_h2(b.z, b.w));
}

// ============================================================================
// fp16 GEMM, cp.async double-buffered. C[m][n] = sum_k A[m][k]*W[n][k]
// CTA 128x128x32, 256 threads, warp tile 64x32.
// mode 0: scatter half to (B,H,T,D), scaled.  mode 1: fp32 row-major + bias.
// ============================================================================
#define GPH 40   // halves per smem row (80 B)

__global__ __launch_bounds__(256) void gemm_h(
    const __half* __restrict__ A, const __half* __restrict__ W,
    const float* __restrict__ bias, void* __restrict__ outv,
    int mode, float scale)
{
    __shared__ __align__(16) __half As[2][128 * GPH];
    __shared__ __align__(16) __half Bs[2][128 * GPH];

    const int tid = threadIdx.x;
    const int wid = tid >> 5;
    const int lid = tid & 31;
    const int qrow = lid >> 2;
    const int qcol = lid & 3;
    const int row0 = blockIdx.y * 128;
    const int col0 = blockIdx.x * 128;
    const int wm0 = (wid & 1) * 64;
    const int wn0 = (wid >> 1) * 32;

    const uint32_t asb = cvta_smem(As);
    const uint32_t bsb = cvta_smem(Bs);
    const uint32_t bufB = 128 * GPH * 2;   // bytes per buffer

    auto prefetch = [&](int kc, int s) {
        const int k0 = kc * 32;
        #pragma unroll
        for (int l = 0; l < 2; l++) {
            int idx = tid + l * 256;       // 0..511
            int r   = idx >> 2;            // 0..127
            int c8  = (idx & 3) * 8;       // 0,8,16,24
            uint32_t off = (uint32_t)(r * GPH + c8) * 2 + s * bufB;
            cp16(asb + off, &A[(size_t)(row0 + r) * EMB + k0 + c8]);
            cp16(bsb + off, &W[(size_t)(col0 + r) * EMB + k0 + c8]);
        }
    };

    float c[4][4][4];
    #pragma unroll
    for (int i = 0; i < 4; i++)
        #pragma unroll
        for (int j = 0; j < 4; j++)
            #pragma unroll
            for (int f = 0; f < 4; f++) c[i][j][f] = 0.f;

    prefetch(0, 0);
    CP_COMMIT();
    int buf = 0;

    for (int kc = 0; kc < EMB / 32; kc++) {
        if (kc + 1 < EMB / 32) {
            prefetch(kc + 1, buf ^ 1);
            CP_COMMIT();
            CP_WAIT(1);
        } else {
            CP_WAIT(0);
        }
        __syncthreads();

        #pragma unroll
        for (int ks = 0; ks < 2; ks++) {
            const int kb = ks * 16 + 2 * qcol;
            uint32_t a[4][4], b[4][2];
            #pragma unroll
            for (int mi = 0; mi < 4; mi++) {
                const __half* ap = &As[buf][(wm0 + mi * 16 + qrow) * GPH + kb];
                a[mi][0] = *(const uint32_t*)ap;
                a[mi][1] = *(const uint32_t*)(ap + 8 * GPH);
                a[mi][2] = *(const uint32_t*)(ap + 8);
                a[mi][3] = *(const uint32_t*)(ap + 8 * GPH + 8);
            }
            #pragma unroll
            for (int ni = 0; ni < 4; ni++) {
                const __half* bp = &Bs[buf][(wn0 + ni * 8 + qrow) * GPH + kb];
                b[ni][0] = *(const uint32_t*)bp;
                b[ni][1] = *(const uint32_t*)(bp + 8);
            }
            #pragma unroll
            for (int mi = 0; mi < 4; mi++)
                #pragma unroll
                for (int ni = 0; ni < 4; ni++)
                    mma_fp16(c[mi][ni][0], c[mi][ni][1], c[mi][ni][2], c[mi][ni][3],
                             a[mi][0], a[mi][1], a[mi][2], a[mi][3],
                             b[ni][0], b[ni][1]);
        }
        __syncthreads();
        buf ^= 1;
    }

    if (mode == 0) {
        __half* out = (__half*)outv;
        #pragma unroll
        for (int mi = 0; mi < 4; mi++) {
            #pragma unroll
            for (int hf = 0; hf < 2; hf++) {
                const int m = row0 + wm0 + mi * 16 + qrow + hf * 8;
                const int bi = m >> 12;
                const int t  = m & (SEQ - 1);
                #pragma unroll
                for (int ni = 0; ni < 4; ni++) {
                    const int n = col0 + wn0 + ni * 8 + qcol * 2;
                    const int h = n >> 6;
                    const int d = n & (HDIM - 1);
                    *(uint32_t*)&out[(((size_t)bi * HEADS + h) * SEQ + t) * HDIM + d] =
                        pack_h2(c[mi][ni][hf * 2] * scale, c[mi][ni][hf * 2 + 1] * scale);
                }
            }
        }
    } else {
        float* out = (float*)outv;
        #pragma unroll
        for (int mi = 0; mi < 4; mi++) {
            #pragma unroll
            for (int hf = 0; hf < 2; hf++) {
                const int m = row0 + wm0 + mi * 16 + qrow + hf * 8;
                #pragma unroll
                for (int ni = 0; ni < 4; ni++) {
                    const int n = col0 + wn0 + ni * 8 + qcol * 2;
                    float2 bb = *(const float2*)&bias[n];
                    *(float2*)&out[(size_t)m * EMB + n] =
                        make_float2(c[mi][ni][hf * 2] + bb.x,
                                    c[mi][ni][hf * 2 + 1] + bb.y);
                }
            }
        }
    }
}

// ============================================================================
// Flash attention, fp16, ldmatrix + cp.async double-buffered K/V.
// 8 warps / 256 threads, 128 q-rows per CTA (two 64-row groups share K/V).
// Dyn smem: Ks0,Vs0,Ks1,Vs1,Ps0,Ps1; tiles [64][FP] halves.
// ============================================================================
#define FP    72
#define FTILE (64 * FP)            // halves per tile
#define FBUFB (2 * FTILE * 2)      // bytes per (Ks,Vs) stage

__global__ __launch_bounds__(256, 2) void flash_mma(
    const __half* __restrict__ Q, const __half* __restrict__ K,
    const __half* __restrict__ V, __half* __restrict__ O)
{
    extern __shared__ __align__(16) char dynsm[];
    __half* Ks0 = (__half*)dynsm;                  // stage s at + s*2*FTILE
    __half* Vs0 = Ks0 + FTILE;
    __half* Ps  = Ks0 + 4 * FTILE;                 // Ps[grp] at + grp*FTILE

    const int qt = blockIdx.x;
    const int bh = blockIdx.y;
    const size_t base = (size_t)bh * SEQ * HDIM;
    const __half* Qb = Q + base;
    const __half* Kb = K + base;
    const __half* Vb = V + base;

    const int tid  = threadIdx.x;
    const int wid  = tid >> 5;
    const int grp  = wid >> 2;
    const int w16  = (wid & 3) * 16;
    const int lid  = tid & 31;
    const int qrow = lid >> 2;
    const int qcol = lid & 3;
    const int q0   = qt * 128;
    const int jtmax = 2 * qt + grp;
    const int last  = 2 * qt + 1;
    const unsigned FULL = 0xffffffffu;

    // ldmatrix per-lane base addresses (stage 0; add buf*FBUFB at use)
    const int i8 = lid & 7;
    const int g1 = (lid >> 3) & 1;
    const int g2 = (lid >> 4) & 1;
    __half* Pg = Ps + grp * FTILE;
    const uint32_t paddr = cvta_smem(Pg) +
        (uint32_t)(((w16 + g1 * 8 + i8) * FP + g2 * 8) * 2);
    uint32_t kaddr[4], vaddr[4];
    {
        const uint32_t kb_ = cvta_smem(Ks0);
        const uint32_t vb_ = cvta_smem(Vs0);
        #pragma unroll
        for (int ntp = 0; ntp < 4; ntp++) {
            kaddr[ntp] = kb_ + (uint32_t)((((2 * ntp + g2) * 8 + i8) * FP + g1 * 8) * 2);
            vaddr[ntp] = vb_ + (uint32_t)(((g1 * 8 + i8) * FP + (2 * ntp + g2) * 8) * 2);
        }
    }

    const uint32_t ksb = cvta_smem(Ks0);
    const uint32_t vsb = cvta_smem(Vs0);
    auto prefetch = [&](int jt, int s) {
        #pragma unroll
        for (int l = 0; l < 2; l++) {
            int idx = tid + l * 256;       // 0..511
            int r   = idx >> 3;            // 0..63
            int c8  = (idx & 7) * 8;
            size_t g = (size_t)(jt * 64 + r) * HDIM + c8;
            uint32_t off = (uint32_t)(r * FP + c8) * 2 + s * FBUFB;
            cp16(ksb + off, &Kb[g]);
            cp16(vsb + off, &Vb[g]);
        }
    };

    prefetch(0, 0);
    CP_COMMIT();

    // ---- stage Q (pre-scaled half) into Ps, pull A-fragments ----
    #pragma unroll
    for (int l = 0; l < 4; l++) {
        int idx = tid + l * 256;           // 0..1023 uint4 slots
        int r   = idx >> 3;                // 0..127
        int c8  = (idx & 7) * 8;
        *(uint4*)&Ps[(r >> 6) * FTILE + (r & 63) * FP + c8] =
            *(const uint4*)&Qb[(size_t)(q0 + r) * HDIM + c8];
    }
    __syncthreads();

    uint32_t aq[4][4];
    #pragma unroll
    for (int ks = 0; ks < 4; ks++)
        ldm_x4(aq[ks][0], aq[ks][1], aq[ks][2], aq[ks][3], paddr + ks * 32);

    float o[8][4];
    #pragma unroll
    for (int nt = 0; nt < 8; nt++)
        #pragma unroll
        for (int f = 0; f < 4; f++) o[nt][f] = 0.f;
    float m_lo = -INFINITY, m_hi = -INFINITY, l_lo = 0.f, l_hi = 0.f;

    int buf = 0;
    for (int jt = 0; jt <= last; jt++) {
        if (jt < last) {
            prefetch(jt + 1, buf ^ 1);
            CP_COMMIT();
            CP_WAIT(1);
        } else {
            CP_WAIT(0);
        }
        __syncthreads();

        if (jt <= jtmax) {
            const uint32_t boff = buf * FBUFB;

            // ---- S = Q K^T ----
            float c[8][4];
            #pragma unroll
            for (int nt = 0; nt < 8; nt++)
                #pragma unroll
                for (int f = 0; f < 4; f++) c[nt][f] = 0.f;

            #pragma unroll
            for (int ks = 0; ks < 4; ks++) {
                #pragma unroll
                for (int ntp = 0; ntp < 4; ntp++) {
                    uint32_t b0, b1, b2, b3;
                    ldm_x4(b0, b1, b2, b3, kaddr[ntp] + boff + ks * 32);
                    mma_fp16(c[2*ntp][0], c[2*ntp][1], c[2*ntp][2], c[2*ntp][3],
                             aq[ks][0], aq[ks][1], aq[ks][2], aq[ks][3], b0, b1);
                    mma_fp16(c[2*ntp+1][0], c[2*ntp+1][1], c[2*ntp+1][2], c[2*ntp+1][3],
                             aq[ks][0], aq[ks][1], aq[ks][2], aq[ks][3], b2, b3);
                }
            }

            // ---- causal mask (diagonal tile of this group) ----
            if (jt == jtmax) {
                #pragma unroll
                for (int nt = 0; nt < 8; nt++) {
                    #pragma unroll
                    for (int f = 0; f < 4; f++) {
                        int kloc = nt * 8 + 2 * qcol + (f & 1);
                        int qloc = w16 + qrow + ((f >> 1) * 8);
                        if (kloc > qloc) c[nt][f] = -INFINITY;
                    }
                }
            }

            // ---- online softmax ----
            float tl = -INFINITY, th = -INFINITY;
            #pragma unroll
            for (int nt = 0; nt < 8; nt++) {
                tl = fmaxf(tl, fmaxf(c[nt][0], c[nt][1]));
                th = fmaxf(th, fmaxf(c[nt][2], c[nt][3]));
            }
            tl = fmaxf(tl, __shfl_xor_sync(FULL, tl, 1, 4));
            tl = fmaxf(tl, __shfl_xor_sync(FULL, tl, 2, 4));
            th = fmaxf(th, __shfl_xor_sync(FULL, th, 1, 4));
            th = fmaxf(th, __shfl_xor_sync(FULL, th, 2, 4));

            float mn_lo = fmaxf(m_lo, tl);
            float mn_hi = fmaxf(m_hi, th);
            float f_lo = __expf(m_lo - mn_lo);
            float f_hi = __expf(m_hi - mn_hi);

            float rs_lo = 0.f, rs_hi = 0.f;
            #pragma unroll
            for (int nt = 0; nt < 8; nt++) {
                float p0 = __expf(c[nt][0] - mn_lo);
                float p1 = __expf(c[nt][1] - mn_lo);
                float p2 = __expf(c[nt][2] - mn_hi);
                float p3 = __expf(c[nt][3] - mn_hi);
                rs_lo += p0 + p1;
                rs_hi += p2 + p3;
                int col = nt * 8 + 2 * qcol;
                *(uint32_t*)&Pg[(w16 + qrow) * FP + col]     = pack_h2(p0, p1);
                *(uint32_t*)&Pg[(w16 + qrow + 8) * FP + col] = pack_h2(p2, p3);
            }
            rs_lo += __shfl_xor_sync(FULL, rs_lo, 1, 4);
            rs_lo += __shfl_xor_sync(FULL, rs_lo, 2, 4);
            rs_hi += __shfl_xor_sync(FULL, rs_hi, 1, 4);
            rs_hi += __shfl_xor_sync(FULL, rs_hi, 2, 4);

            l_lo = l_lo * f_lo + rs_lo;
            l_hi = l_hi * f_hi + rs_hi;
            m_lo = mn_lo;
            m_hi = mn_hi;
            #pragma unroll
            for (int nt = 0; nt < 8; nt++) {
                o[nt][0] *= f_lo; o[nt][1] *= f_lo;
                o[nt][2] *= f_hi; o[nt][3] *= f_hi;
            }
            __syncwarp();      // Ps rows warp-private: order STS -> ldmatrix

            // ---- O += P V ----
            #pragma unroll
            for (int ks = 0; ks < 4; ks++) {
                uint32_t a0, a1, a2, a3;
                ldm_x4(a0, a1, a2, a3, paddr + ks * 32);
                #pragma unroll
                for (int ntp = 0; ntp < 4; ntp++) {
                    uint32_t v0, v1, v2, v3;
                    ldm_x4_t(v0, v1, v2, v3, vaddr[ntp] + boff + ks * (16 * FP * 2));
                    mma_fp16(o[2*ntp][0], o[2*ntp][1], o[2*ntp][2], o[2*ntp][3],
                             a0, a1, a2, a3, v0, v1);
                    mma_fp16(o[2*ntp+1][0], o[2*ntp+1][1], o[2*ntp+1][2], o[2*ntp+1][3],
                             a0, a1, a2, a3, v2, v3);
                }
            }
        }
        __syncthreads();
        buf ^= 1;
    }

    // ---- epilogue: write half (B,T,E) ----
    const float inv_lo = 1.f / l_lo;
    const float inv_hi = 1.f / l_hi;
    const int b = bh >> 4;
    const int h = bh & (HEADS - 1);
    const int row_lo = q0 + grp * 64 + w16 + qrow;
    const int row_hi = row_lo + 8;
    #pragma unroll
    for (int nt = 0; nt < 8; nt++) {
        const int e = h * HDIM + nt * 8 + 2 * qcol;
        *(uint32_t*)&O[((size_t)(b * SEQ) + row_lo) * EMB + e] =
            pack_h2(o[nt][0] * inv_lo, o[nt][1] * inv_lo);
        *(uint32_t*)&O[((size_t)(b * SEQ) + row_hi) * EMB + e] =
            pack_h2(o[nt][2] * inv_hi, o[nt][3] * inv_hi);
    }
}

// ---------------- launch -----------------------------------------------------
extern "C" void kernel_launch(void* const* d_in, const int* in_sizes, int n_in,
                              void* d_out, int out_size)
{
    const float* x  = (const float*)d_in[0];
    const float* Wq = (const float*)d_in[1];
    const float* Wk = (const float*)d_in[2];
    const float* Wv = (const float*)d_in[3];
    const float* Wo = (const float*)d_in[4];
    const float* bo = (const float*)d_in[5];
    float* out = (float*)d_out;

    __half *Qp, *Kp, *Vp, *Ap, *xh, *Wh;
    cudaGetSymbolAddress((void**)&Qp, g_Qh);
    cudaGetSymbolAddress((void**)&Kp, g_Kh);
    cudaGetSymbolAddress((void**)&Vp, g_Vh);
    cudaGetSymbolAddress((void**)&Ap, g_AOh);
    cudaGetSymbolAddress((void**)&xh, g_xh);
    cudaGetSymbolAddress((void**)&Wh, g_Wh);

    const int nW = EMB * EMB;          // 1048576
    f2h<<<(MROWS * EMB) / (256 * 8), 256>>>(x, xh, MROWS * EMB);
    f2h<<<nW / (256 * 8), 256>>>(Wq, Wh + 0 * (size_t)nW, nW);
    f2h<<<nW / (256 * 8), 256>>>(Wk, Wh + 1 * (size_t)nW, nW);
    f2h<<<nW / (256 * 8), 256>>>(Wv, Wh + 2 * (size_t)nW, nW);
    f2h<<<nW / (256 * 8), 256>>>(Wo, Wh + 3 * (size_t)nW, nW);

    dim3 gg(EMB / 128, MROWS / 128);   // (8, 64)
    gemm_h<<<gg, 256>>>(xh, Wh + 0 * (size_t)nW, nullptr, Qp, 0, 0.125f);
    gemm_h<<<gg, 256>>>(xh, Wh + 1 * (size_t)nW, nullptr, Kp, 0, 1.0f);
    gemm_h<<<gg, 256>>>(xh, Wh + 2 * (size_t)nW, nullptr, Vp, 0, 1.0f);

    const int fsm = 6 * FTILE * 2;     // 55296 B
    cudaFuncSetAttribute(flash_mma, cudaFuncAttributeMaxDynamicSharedMemorySize, fsm);
    flash_mma<<<dim3(SEQ / 128, BATCH * HEADS), 256, fsm>>>(Qp, Kp, Vp, Ap);

    gemm_h<<<gg, 256>>>(Ap, Wh + 3 * (size_t)nW, bo, out, 1, 1.0f);
}

// round 9
// speedup vs baseline: 2.8258x; 1.0033x over previous
#include <cuda_runtime.h>
#include <cuda_bf16.h>
#include <cuda_fp16.h>
#include <math.h>
#include <cstdint>

// Problem constants
#define BATCH 2
#define SEQ   4096
#define EMB   1024
#define HEADS 16
#define HDIM  64
#define MROWS (BATCH*SEQ)   // 8192

// ---------------- scratch (static device globals; no runtime allocation) ----
__device__ __half g_Qh[(size_t)BATCH*HEADS*SEQ*HDIM];  // (B,H,T,D), pre-scaled 1/8
__device__ __half g_Kh[(size_t)BATCH*HEADS*SEQ*HDIM];
__device__ __half g_Vh[(size_t)BATCH*HEADS*SEQ*HDIM];
__device__ __half g_AOh[(size_t)BATCH*SEQ*EMB];        // (B,T,E)
__device__ __half g_xh[(size_t)MROWS*EMB];
__device__ __half g_Wh[4][(size_t)EMB*EMB];            // Wq,Wk,Wv,Wo as half

__device__ __forceinline__ uint32_t pack_h2(float a, float b) {
    __half2 h = __floats2half2_rn(a, b);
    return *(uint32_t*)&h;
}

__device__ __forceinline__ uint32_t cvta_smem(const void* p) {
    uint32_t a;
    asm("{ .reg .u64 t; cvta.to.shared.u64 t, %1; cvt.u32.u64 %0, t; }"
        : "=r"(a) : "l"(p));
    return a;
}

__device__ __forceinline__ void cp16(uint32_t smem, const void* g) {
    asm volatile("cp.async.cg.shared.global [%0], [%1], 16;" :: "r"(smem), "l"(g));
}
#define CP_COMMIT() asm volatile("cp.async.commit_group;" ::: "memory")
#define CP_WAIT(n)  asm volatile("cp.async.wait_group %0;" :: "n"(n) : "memory")

__device__ __forceinline__ void ldm_x4(
    uint32_t& r0, uint32_t& r1, uint32_t& r2, uint32_t& r3, uint32_t addr)
{
    asm volatile("ldmatrix.sync.aligned.m8n8.x4.shared.b16 {%0,%1,%2,%3}, [%4];"
        : "=r"(r0), "=r"(r1), "=r"(r2), "=r"(r3) : "r"(addr));
}

__device__ __forceinline__ void ldm_x4_t(
    uint32_t& r0, uint32_t& r1, uint32_t& r2, uint32_t& r3, uint32_t addr)
{
    asm volatile("ldmatrix.sync.aligned.m8n8.x4.trans.shared.b16 {%0,%1,%2,%3}, [%4];"
        : "=r"(r0), "=r"(r1), "=r"(r2), "=r"(r3) : "r"(addr));
}

__device__ __forceinline__ void mma_fp16(
    float& c0, float& c1, float& c2, float& c3,
    uint32_t a0, uint32_t a1, uint32_t a2, uint32_t a3,
    uint32_t b0, uint32_t b1)
{
    asm volatile(
        "mma.sync.aligned.m16n8k16.row.col.f32.f16.f16.f32 "
        "{%0,%1,%2,%3}, {%4,%5,%6,%7}, {%8,%9}, {%0,%1,%2,%3};"
        : "+f"(c0), "+f"(c1), "+f"(c2), "+f"(c3)
        : "r"(a0), "r"(a1), "r"(a2), "r"(a3), "r"(b0), "r"(b1));
}

// ---------------- fp32 -> fp16 convert (8 elems/thread) ----------------------
__global__ __launch_bounds__(256) void f2h(
    const float* __restrict__ in, __half* __restrict__ out, int n)
{
    int i = (blockIdx.x * 256 + threadIdx.x) * 8;
    if (i >= n) return;
    float4 a = *(const float4*)&in[i];
    float4 b = *(const float4*)&in[i + 4];
    *(uint4*)&out[i] = make_uint4(pack_h2(a.x, a.y), pack_h2(a.z, a.w),
                                  pack_h2(b.x, b.y), pack_h2(b.z, b.w));
}

// ============================================================================
// fp16 GEMM, cp.async double-buffered, ldmatrix fragments.
// C[m][n] = sum_k A[m][k]*W[n][k].  CTA 128x128x32, 256 thr, warp tile 64x32.
// mode 0: scatter half to (B,H,T,D), scaled.  mode 1: fp32 row-major + bias.
// ============================================================================
#define GPH 40   // halves per smem row (80 B) — ldmatrix conflict-free

__global__ __launch_bounds__(256) void gemm_h(
    const __half* __restrict__ A, const __half* __restrict__ W,
    const float* __restrict__ bias, void* __restrict__ outv,
    int mode, float scale)
{
    __shared__ __align__(16) __half As[2][128 * GPH];
    __shared__ __align__(16) __half Bs[2][128 * GPH];

    const int tid = threadIdx.x;
    const int wid = tid >> 5;
    const int lid = tid & 31;
    const int qrow = lid >> 2;
    const int qcol = lid & 3;
    const int row0 = blockIdx.y * 128;
    const int col0 = blockIdx.x * 128;
    const int wm0 = (wid & 1) * 64;
    const int wn0 = (wid >> 1) * 32;

    const uint32_t asb = cvta_smem(As);
    const uint32_t bsb = cvta_smem(Bs);
    const uint32_t bufB = 128 * GPH * 2;   // bytes per buffer

    // ldmatrix per-lane base addresses
    const int i16 = lid & 15;
    const int g8  = ((lid >> 4) & 1) * 8;
    uint32_t aaddr[4], baddr[2];
    #pragma unroll
    for (int mi = 0; mi < 4; mi++)
        aaddr[mi] = asb + (uint32_t)(((wm0 + mi * 16 + i16) * GPH + g8) * 2);
    #pragma unroll
    for (int nip = 0; nip < 2; nip++)
        baddr[nip] = bsb + (uint32_t)(((wn0 + nip * 16 + i16) * GPH + g8) * 2);

    auto prefetch = [&](int kc, int s) {
        const int k0 = kc * 32;
        #pragma unroll
        for (int l = 0; l < 2; l++) {
            int idx = tid + l * 256;       // 0..511
            int r   = idx >> 2;            // 0..127
            int c8  = (idx & 3) * 8;       // 0,8,16,24
            uint32_t off = (uint32_t)(r * GPH + c8) * 2 + s * bufB;
            cp16(asb + off, &A[(size_t)(row0 + r) * EMB + k0 + c8]);
            cp16(bsb + off, &W[(size_t)(col0 + r) * EMB + k0 + c8]);
        }
    };

    float c[4][4][4];
    #pragma unroll
    for (int i = 0; i < 4; i++)
        #pragma unroll
        for (int j = 0; j < 4; j++)
            #pragma unroll
            for (int f = 0; f < 4; f++) c[i][j][f] = 0.f;

    prefetch(0, 0);
    CP_COMMIT();
    int buf = 0;

    for (int kc = 0; kc < EMB / 32; kc++) {
        if (kc + 1 < EMB / 32) {
            prefetch(kc + 1, buf ^ 1);
            CP_COMMIT();
            CP_WAIT(1);
        } else {
            CP_WAIT(0);
        }
        __syncthreads();
        const uint32_t boff = buf * bufB;

        #pragma unroll
        for (int ks = 0; ks < 2; ks++) {
            const uint32_t koff = boff + ks * 32;
            uint32_t a[4][4], b[4][2];
            #pragma unroll
            for (int mi = 0; mi < 4; mi++)
                ldm_x4(a[mi][0], a[mi][1], a[mi][2], a[mi][3], aaddr[mi] + koff);
            #pragma unroll
            for (int nip = 0; nip < 2; nip++) {
                uint32_t r0, r1, r2, r3;
                ldm_x4(r0, r1, r2, r3, baddr[nip] + koff);
                b[2*nip][0] = r0;   b[2*nip][1] = r2;
                b[2*nip+1][0] = r1; b[2*nip+1][1] = r3;
            }
            #pragma unroll
            for (int mi = 0; mi < 4; mi++)
                #pragma unroll
                for (int ni = 0; ni < 4; ni++)
                    mma_fp16(c[mi][ni][0], c[mi][ni][1], c[mi][ni][2], c[mi][ni][3],
                             a[mi][0], a[mi][1], a[mi][2], a[mi][3],
                             b[ni][0], b[ni][1]);
        }
        __syncthreads();
        buf ^= 1;
    }

    if (mode == 0) {
        __half* out = (__half*)outv;
        #pragma unroll
        for (int mi = 0; mi < 4; mi++) {
            #pragma unroll
            for (int hf = 0; hf < 2; hf++) {
                const int m = row0 + wm0 + mi * 16 + qrow + hf * 8;
                const int bi = m >> 12;
                const int t  = m & (SEQ - 1);
                #pragma unroll
                for (int ni = 0; ni < 4; ni++) {
                    const int n = col0 + wn0 + ni * 8 + qcol * 2;
                    const int h = n >> 6;
                    const int d = n & (HDIM - 1);
                    *(uint32_t*)&out[(((size_t)bi * HEADS + h) * SEQ + t) * HDIM + d] =
                        pack_h2(c[mi][ni][hf * 2] * scale, c[mi][ni][hf * 2 + 1] * scale);
                }
            }
        }
    } else {
        float* out = (float*)outv;
        #pragma unroll
        for (int mi = 0; mi < 4; mi++) {
            #pragma unroll
            for (int hf = 0; hf < 2; hf++) {
                const int m = row0 + wm0 + mi * 16 + qrow + hf * 8;
                #pragma unroll
                for (int ni = 0; ni < 4; ni++) {
                    const int n = col0 + wn0 + ni * 8 + qcol * 2;
                    float2 bb = *(const float2*)&bias[n];
                    *(float2*)&out[(size_t)m * EMB + n] =
                        make_float2(c[mi][ni][hf * 2] + bb.x,
                                    c[mi][ni][hf * 2 + 1] + bb.y);
                }
            }
        }
    }
}

// ============================================================================
// Flash attention, fp16, ldmatrix + cp.async double-buffered K/V.
// 8 warps / 256 threads, 128 q-rows per CTA; qt REVERSED (heavy CTAs first).
// ============================================================================
#define FP    72
#define FTILE (64 * FP)            // halves per tile
#define FBUFB (2 * FTILE * 2)      // bytes per (Ks,Vs) stage

__global__ __launch_bounds__(256, 2) void flash_mma(
    const __half* __restrict__ Q, const __half* __restrict__ K,
    const __half* __restrict__ V, __half* __restrict__ O)
{
    extern __shared__ __align__(16) char dynsm[];
    __half* Ks0 = (__half*)dynsm;                  // stage s at + s*2*FTILE
    __half* Vs0 = Ks0 + FTILE;
    __half* Ps  = Ks0 + 4 * FTILE;                 // Ps[grp] at + grp*FTILE

    const int qt = gridDim.x - 1 - blockIdx.x;     // heavy tiles first (LPT)
    const int bh = blockIdx.y;
    const size_t base = (size_t)bh * SEQ * HDIM;
    const __half* Qb = Q + base;
    const __half* Kb = K + base;
    const __half* Vb = V + base;

    const int tid  = threadIdx.x;
    const int wid  = tid >> 5;
    const int grp  = wid >> 2;
    const int w16  = (wid & 3) * 16;
    const int lid  = tid & 31;
    const int qrow = lid >> 2;
    const int qcol = lid & 3;
    const int q0   = qt * 128;
    const int jtmax = 2 * qt + grp;
    const int last  = 2 * qt + 1;
    const unsigned FULL = 0xffffffffu;

    // ldmatrix per-lane base addresses (stage 0; add buf*FBUFB at use)
    const int i8 = lid & 7;
    const int g1 = (lid >> 3) & 1;
    const int g2 = (lid >> 4) & 1;
    __half* Pg = Ps + grp * FTILE;
    const uint32_t paddr = cvta_smem(Pg) +
        (uint32_t)(((w16 + g1 * 8 + i8) * FP + g2 * 8) * 2);
    uint32_t kaddr[4], vaddr[4];
    {
        const uint32_t kb_ = cvta_smem(Ks0);
        const uint32_t vb_ = cvta_smem(Vs0);
        #pragma unroll
        for (int ntp = 0; ntp < 4; ntp++) {
            kaddr[ntp] = kb_ + (uint32_t)((((2 * ntp + g2) * 8 + i8) * FP + g1 * 8) * 2);
            vaddr[ntp] = vb_ + (uint32_t)(((g1 * 8 + i8) * FP + (2 * ntp + g2) * 8) * 2);
        }
    }

    const uint32_t ksb = cvta_smem(Ks0);
    const uint32_t vsb = cvta_smem(Vs0);
    auto prefetch = [&](int jt, int s) {
        #pragma unroll
        for (int l = 0; l < 2; l++) {
            int idx = tid + l * 256;       // 0..511
            int r   = idx >> 3;            // 0..63
            int c8  = (idx & 7) * 8;
            size_t g = (size_t)(jt * 64 + r) * HDIM + c8;
            uint32_t off = (uint32_t)(r * FP + c8) * 2 + s * FBUFB;
            cp16(ksb + off, &Kb[g]);
            cp16(vsb + off, &Vb[g]);
        }
    };

    prefetch(0, 0);
    CP_COMMIT();

    // ---- stage Q (pre-scaled half) into Ps, pull A-fragments ----
    #pragma unroll
    for (int l = 0; l < 4; l++) {
        int idx = tid + l * 256;           // 0..1023 uint4 slots
        int r   = idx >> 3;                // 0..127
        int c8  = (idx & 7) * 8;
        *(uint4*)&Ps[(r >> 6) * FTILE + (r & 63) * FP + c8] =
            *(const uint4*)&Qb[(size_t)(q0 + r) * HDIM + c8];
    }
    __syncthreads();

    uint32_t aq[4][4];
    #pragma unroll
    for (int ks = 0; ks < 4; ks++)
        ldm_x4(aq[ks][0], aq[ks][1], aq[ks][2], aq[ks][3], paddr + ks * 32);

    float o[8][4];
    #pragma unroll
    for (int nt = 0; nt < 8; nt++)
        #pragma unroll
        for (int f = 0; f < 4; f++) o[nt][f] = 0.f;
    float m_lo = -INFINITY, m_hi = -INFINITY, l_lo = 0.f, l_hi = 0.f;

    int buf = 0;
    for (int jt = 0; jt <= last; jt++) {
        if (jt < last) {
            prefetch(jt + 1, buf ^ 1);
            CP_COMMIT();
            CP_WAIT(1);
        } else {
            CP_WAIT(0);
        }
        __syncthreads();

        if (jt <= jtmax) {
            const uint32_t boff = buf * FBUFB;

            // ---- S = Q K^T ----
            float c[8][4];
            #pragma unroll
            for (int nt = 0; nt < 8; nt++)
                #pragma unroll
                for (int f = 0; f < 4; f++) c[nt][f] = 0.f;

            #pragma unroll
            for (int ks = 0; ks < 4; ks++) {
                #pragma unroll
                for (int ntp = 0; ntp < 4; ntp++) {
                    uint32_t b0, b1, b2, b3;
                    ldm_x4(b0, b1, b2, b3, kaddr[ntp] + boff + ks * 32);
                    mma_fp16(c[2*ntp][0], c[2*ntp][1], c[2*ntp][2], c[2*ntp][3],
                             aq[ks][0], aq[ks][1], aq[ks][2], aq[ks][3], b0, b1);
                    mma_fp16(c[2*ntp+1][0], c[2*ntp+1][1], c[2*ntp+1][2], c[2*ntp+1][3],
                             aq[ks][0], aq[ks][1], aq[ks][2], aq[ks][3], b2, b3);
                }
            }

            // ---- causal mask (diagonal tile of this group) ----
            if (jt == jtmax) {
                #pragma unroll
                for (int nt = 0; nt < 8; nt++) {
                    #pragma unroll
                    for (int f = 0; f < 4; f++) {
                        int kloc = nt * 8 + 2 * qcol + (f & 1);
                        int qloc = w16 + qrow + ((f >> 1) * 8);
                        if (kloc > qloc) c[nt][f] = -INFINITY;
                    }
                }
            }

            // ---- online softmax ----
            float tl = -INFINITY, th = -INFINITY;
            #pragma unroll
            for (int nt = 0; nt < 8; nt++) {
                tl = fmaxf(tl, fmaxf(c[nt][0], c[nt][1]));
                th = fmaxf(th, fmaxf(c[nt][2], c[nt][3]));
            }
            tl = fmaxf(tl, __shfl_xor_sync(FULL, tl, 1, 4));
            tl = fmaxf(tl, __shfl_xor_sync(FULL, tl, 2, 4));
            th = fmaxf(th, __shfl_xor_sync(FULL, th, 1, 4));
            th = fmaxf(th, __shfl_xor_sync(FULL, th, 2, 4));

            float mn_lo = fmaxf(m_lo, tl);
            float mn_hi = fmaxf(m_hi, th);
            float f_lo = __expf(m_lo - mn_lo);
            float f_hi = __expf(m_hi - mn_hi);

            float rs_lo = 0.f, rs_hi = 0.f;
            #pragma unroll
            for (int nt = 0; nt < 8; nt++) {
                float p0 = __expf(c[nt][0] - mn_lo);
                float p1 = __expf(c[nt][1] - mn_lo);
                float p2 = __expf(c[nt][2] - mn_hi);
                float p3 = __expf(c[nt][3] - mn_hi);
                rs_lo += p0 + p1;
                rs_hi += p2 + p3;
                int col = nt * 8 + 2 * qcol;
                *(uint32_t*)&Pg[(w16 + qrow) * FP + col]     = pack_h2(p0, p1);
                *(uint32_t*)&Pg[(w16 + qrow + 8) * FP + col] = pack_h2(p2, p3);
            }
            rs_lo += __shfl_xor_sync(FULL, rs_lo, 1, 4);
            rs_lo += __shfl_xor_sync(FULL, rs_lo, 2, 4);
            rs_hi += __shfl_xor_sync(FULL, rs_hi, 1, 4);
            rs_hi += __shfl_xor_sync(FULL, rs_hi, 2, 4);

            l_lo = l_lo * f_lo + rs_lo;
            l_hi = l_hi * f_hi + rs_hi;
            m_lo = mn_lo;
            m_hi = mn_hi;
            #pragma unroll
            for (int nt = 0; nt < 8; nt++) {
                o[nt][0] *= f_lo; o[nt][1] *= f_lo;
                o[nt][2] *= f_hi; o[nt][3] *= f_hi;
            }
            __syncwarp();      // Ps rows warp-private: order STS -> ldmatrix

            // ---- O += P V ----
            #pragma unroll
            for (int ks = 0; ks < 4; ks++) {
                uint32_t a0, a1, a2, a3;
                ldm_x4(a0, a1, a2, a3, paddr + ks * 32);
                #pragma unroll
                for (int ntp = 0; ntp < 4; ntp++) {
                    uint32_t v0, v1, v2, v3;
                    ldm_x4_t(v0, v1, v2, v3, vaddr[ntp] + boff + ks * (16 * FP * 2));
                    mma_fp16(o[2*ntp][0], o[2*ntp][1], o[2*ntp][2], o[2*ntp][3],
                             a0, a1, a2, a3, v0, v1);
                    mma_fp16(o[2*ntp+1][0], o[2*ntp+1][1], o[2*ntp+1][2], o[2*ntp+1][3],
                             a0, a1, a2, a3, v2, v3);
                }
            }
        }
        __syncthreads();
        buf ^= 1;
    }

    // ---- epilogue: write half (B,T,E) ----
    const float inv_lo = 1.f / l_lo;
    const float inv_hi = 1.f / l_hi;
    const int b = bh >> 4;
    const int h = bh & (HEADS - 1);
    const int row_lo = q0 + grp * 64 + w16 + qrow;
    const int row_hi = row_lo + 8;
    #pragma unroll
    for (int nt = 0; nt < 8; nt++) {
        const int e = h * HDIM + nt * 8 + 2 * qcol;
        *(uint32_t*)&O[((size_t)(b * SEQ) + row_lo) * EMB + e] =
            pack_h2(o[nt][0] * inv_lo, o[nt][1] * inv_lo);
        *(uint32_t*)&O[((size_t)(b * SEQ) + row_hi) * EMB + e] =
            pack_h2(o[nt][2] * inv_hi, o[nt][3] * inv_hi);
    }
}

// ---------------- launch -----------------------------------------------------
extern "C" void kernel_launch(void* const* d_in, const int* in_sizes, int n_in,
                              void* d_out, int out_size)
{
    const float* x  = (const float*)d_in[0];
    const float* Wq = (const float*)d_in[1];
    const float* Wk = (const float*)d_in[2];
    const float* Wv = (const float*)d_in[3];
    const float* Wo = (const float*)d_in[4];
    const float* bo = (const float*)d_in[5];
    float* out = (float*)d_out;

    __half *Qp, *Kp, *Vp, *Ap, *xh, *Wh;
    cudaGetSymbolAddress((void**)&Qp, g_Qh);
    cudaGetSymbolAddress((void**)&Kp, g_Kh);
    cudaGetSymbolAddress((void**)&Vp, g_Vh);
    cudaGetSymbolAddress((void**)&Ap, g_AOh);
    cudaGetSymbolAddress((void**)&xh, g_xh);
    cudaGetSymbolAddress((void**)&Wh, g_Wh);

    const int nW = EMB * EMB;          // 1048576
    f2h<<<(MROWS * EMB) / (256 * 8), 256>>>(x, xh, MROWS * EMB);
    f2h<<<nW / (256 * 8), 256>>>(Wq, Wh + 0 * (size_t)nW, nW);
    f2h<<<nW / (256 * 8), 256>>>(Wk, Wh + 1 * (size_t)nW, nW);
    f2h<<<nW / (256 * 8), 256>>>(Wv, Wh + 2 * (size_t)nW, nW);
    f2h<<<nW / (256 * 8), 256>>>(Wo, Wh + 3 * (size_t)nW, nW);

    dim3 gg(EMB / 128, MROWS / 128);   // (8, 64)
    gemm_h<<<gg, 256>>>(xh, Wh + 0 * (size_t)nW, nullptr, Qp, 0, 0.125f);
    gemm_h<<<gg, 256>>>(xh, Wh + 1 * (size_t)nW, nullptr, Kp, 0, 1.0f);
    gemm_h<<<gg, 256>>>(xh, Wh + 2 * (size_t)nW, nullptr, Vp, 0, 1.0f);

    const int fsm = 6 * FTILE * 2;     // 55296 B
    cudaFuncSetAttribute(flash_mma, cudaFuncAttributeMaxDynamicSharedMemorySize, fsm);
    flash_mma<<<dim3(SEQ / 128, BATCH * HEADS), 256, fsm>>>(Qp, Kp, Vp, Ap);

    gemm_h<<<gg, 256>>>(Ap, Wh + 3 * (size_t)nW, bo, out, 1, 1.0f);
}

// round 10
// speedup vs baseline: 2.9819x; 1.0552x over previous
#include <cuda_runtime.h>
#include <cuda_bf16.h>
#include <cuda_fp16.h>
#include <math.h>
#include <cstdint>

// Problem constants
#define BATCH 2
#define SEQ   4096
#define EMB   1024
#define HEADS 16
#define HDIM  64
#define MROWS (BATCH*SEQ)   // 8192

// ---------------- scratch (static device globals; no runtime allocation) ----
__device__ __half g_Qh[(size_t)BATCH*HEADS*SEQ*HDIM];  // (B,H,T,D), scaled 0.125*log2e
__device__ __half g_Kh[(size_t)BATCH*HEADS*SEQ*HDIM];
__device__ __half g_Vh[(size_t)BATCH*HEADS*SEQ*HDIM];
__device__ __half g_AOh[(size_t)BATCH*SEQ*EMB];        // (B,T,E)
__device__ __half g_xh[(size_t)MROWS*EMB];
__device__ __half g_Wh[4][(size_t)EMB*EMB];            // Wq,Wk,Wv,Wo as half

__device__ __forceinline__ uint32_t pack_h2(float a, float b) {
    __half2 h = __floats2half2_rn(a, b);
    return *(uint32_t*)&h;
}

__device__ __forceinline__ uint32_t h2exp2(uint32_t x) {
    uint32_t r;
    asm("ex2.approx.f16x2 %0, %1;" : "=r"(r) : "r"(x));
    return r;
}

__device__ __forceinline__ float ex2f(float x) {
    float r;
    asm("ex2.approx.f32 %0, %1;" : "=f"(r) : "f"(x));
    return r;
}

__device__ __forceinline__ uint32_t cvta_smem(const void* p) {
    uint32_t a;
    asm("{ .reg .u64 t; cvta.to.shared.u64 t, %1; cvt.u32.u64 %0, t; }"
        : "=r"(a) : "l"(p));
    return a;
}

__device__ __forceinline__ void cp16(uint32_t smem, const void* g) {
    asm volatile("cp.async.cg.shared.global [%0], [%1], 16;" :: "r"(smem), "l"(g));
}
#define CP_COMMIT() asm volatile("cp.async.commit_group;" ::: "memory")
#define CP_WAIT(n)  asm volatile("cp.async.wait_group %0;" :: "n"(n) : "memory")

__device__ __forceinline__ void ldm_x4(
    uint32_t& r0, uint32_t& r1, uint32_t& r2, uint32_t& r3, uint32_t addr)
{
    asm volatile("ldmatrix.sync.aligned.m8n8.x4.shared.b16 {%0,%1,%2,%3}, [%4];"
        : "=r"(r0), "=r"(r1), "=r"(r2), "=r"(r3) : "r"(addr));
}

__device__ __forceinline__ void ldm_x4_t(
    uint32_t& r0, uint32_t& r1, uint32_t& r2, uint32_t& r3, uint32_t addr)
{
    asm volatile("ldmatrix.sync.aligned.m8n8.x4.trans.shared.b16 {%0,%1,%2,%3}, [%4];"
        : "=r"(r0), "=r"(r1), "=r"(r2), "=r"(r3) : "r"(addr));
}

__device__ __forceinline__ void mma_fp16(
    float& c0, float& c1, float& c2, float& c3,
    uint32_t a0, uint32_t a1, uint32_t a2, uint32_t a3,
    uint32_t b0, uint32_t b1)
{
    asm volatile(
        "mma.sync.aligned.m16n8k16.row.col.f32.f16.f16.f32 "
        "{%0,%1,%2,%3}, {%4,%5,%6,%7}, {%8,%9}, {%0,%1,%2,%3};"
        : "+f"(c0), "+f"(c1), "+f"(c2), "+f"(c3)
        : "r"(a0), "r"(a1), "r"(a2), "r"(a3), "r"(b0), "r"(b1));
}

// ---------------- fused fp32 -> fp16 convert (x + 4 weights, 16/thread) -----
#define NX   (MROWS*EMB)     // 8388608
#define NWEL (EMB*EMB)       // 1048576 = 2^20

__global__ __launch_bounds__(256) void cvt_all(
    const float* __restrict__ x,
    const float* __restrict__ wq, const float* __restrict__ wk,
    const float* __restrict__ wv, const float* __restrict__ wo,
    __half* __restrict__ xh, __half* __restrict__ wh)
{
    size_t i = ((size_t)blockIdx.x * 256 + threadIdx.x) * 16;
    const float* src;
    __half* dst;
    size_t off;
    if (i < NX) { src = x; dst = xh; off = i; }
    else {
        size_t j = i - NX;
        int w = (int)(j >> 20);
        src = (w == 0) ? wq : (w == 1) ? wk : (w == 2) ? wv : wo;
        dst = wh + (size_t)w * NWEL;
        off = j & (NWEL - 1);
    }
    #pragma unroll
    for (int l = 0; l < 2; l++) {
        float4 a = *(const float4*)&src[off + l * 8];
        float4 b = *(const float4*)&src[off + l * 8 + 4];
        *(uint4*)&dst[off + l * 8] = make_uint4(
            pack_h2(a.x, a.y), pack_h2(a.z, a.w),
            pack_h2(b.x, b.y), pack_h2(b.z, b.w));
    }
}

// ============================================================================
// fp16 GEMM, 3-stage cp.async ring (one sync per chunk), ldmatrix fragments.
// C[m][n] = sum_k A[m][k]*W[n][k].  CTA 128x128x32, 256 thr, warp tile 64x32.
// mode 0: scatter half to (B,H,T,D), scaled.  mode 1: fp32 row-major + bias.
// ============================================================================
#define GPH    40                      // halves per smem row (80 B)
#define GSTGB  (128 * GPH * 2)         // bytes per operand per stage (10240)
#define GSB    (2 * GSTGB)             // bytes per stage (A+B) = 20480
#define GSMEM  (3 * GSB)               // 61440
#define NCHUNK (EMB / 32)              // 32

__global__ __launch_bounds__(256) void gemm_h(
    const __half* __restrict__ A, const __half* __restrict__ W,
    const float* __restrict__ bias, void* __restrict__ outv,
    int mode, float scale)
{
    extern __shared__ __align__(16) char gsm[];
    const uint32_t asb = cvta_smem(gsm);           // A of stage 0
    const uint32_t bsb = asb + GSTGB;              // B of stage 0

    const int tid = threadIdx.x;
    const int wid = tid >> 5;
    const int lid = tid & 31;
    const int qrow = lid >> 2;
    const int qcol = lid & 3;
    const int row0 = blockIdx.y * 128;
    const int col0 = blockIdx.x * 128;
    const int wm0 = (wid & 1) * 64;
    const int wn0 = (wid >> 1) * 32;

    // ldmatrix per-lane base addresses (stage 0)
    const int i16 = lid & 15;
    const int g8  = ((lid >> 4) & 1) * 8;
    uint32_t aaddr[4], baddr[2];
    #pragma unroll
    for (int mi = 0; mi < 4; mi++)
        aaddr[mi] = asb + (uint32_t)(((wm0 + mi * 16 + i16) * GPH + g8) * 2);
    #pragma unroll
    for (int nip = 0; nip < 2; nip++)
        baddr[nip] = bsb + (uint32_t)(((wn0 + nip * 16 + i16) * GPH + g8) * 2);

    auto prefetch = [&](int kc, int slot) {
        const int k0 = kc * 32;
        const uint32_t so = slot * GSB;
        #pragma unroll
        for (int l = 0; l < 2; l++) {
            int idx = tid + l * 256;       // 0..511
            int r   = idx >> 2;            // 0..127
            int c8  = (idx & 3) * 8;       // 0,8,16,24
            uint32_t off = (uint32_t)(r * GPH + c8) * 2 + so;
            cp16(asb + off, &A[(size_t)(row0 + r) * EMB + k0 + c8]);
            cp16(bsb + off, &W[(size_t)(col0 + r) * EMB + k0 + c8]);
        }
    };

    float c[4][4][4];
    #pragma unroll
    for (int i = 0; i < 4; i++)
        #pragma unroll
        for (int j = 0; j < 4; j++)
            #pragma unroll
            for (int f = 0; f < 4; f++) c[i][j][f] = 0.f;

    prefetch(0, 0); CP_COMMIT();
    prefetch(1, 1); CP_COMMIT();

    for (int kc = 0; kc < NCHUNK; kc++) {
        if (kc + 1 < NCHUNK) { CP_WAIT(1); } else { CP_WAIT(0); }
        __syncthreads();                   // chunk kc ready for all warps
        if (kc + 2 < NCHUNK) {             // slot (kc+2)%3 == (kc-1)%3, drained
            prefetch(kc + 2, (kc + 2) % 3);
            CP_COMMIT();
        }
        const uint32_t so = (kc % 3) * GSB;

        #pragma unroll
        for (int ks = 0; ks < 2; ks++) {
            const uint32_t koff = so + ks * 32;
            uint32_t a[4][4], b[4][2];
            #pragma unroll
            for (int mi = 0; mi < 4; mi++)
                ldm_x4(a[mi][0], a[mi][1], a[mi][2], a[mi][3], aaddr[mi] + koff);
            #pragma unroll
            for (int nip = 0; nip < 2; nip++) {
                uint32_t r0, r1, r2, r3;
                ldm_x4(r0, r1, r2, r3, baddr[nip] + koff);
                b[2*nip][0] = r0;   b[2*nip][1] = r2;
                b[2*nip+1][0] = r1; b[2*nip+1][1] = r3;
            }
            #pragma unroll
            for (int mi = 0; mi < 4; mi++)
                #pragma unroll
                for (int ni = 0; ni < 4; ni++)
                    mma_fp16(c[mi][ni][0], c[mi][ni][1], c[mi][ni][2], c[mi][ni][3],
                             a[mi][0], a[mi][1], a[mi][2], a[mi][3],
                             b[ni][0], b[ni][1]);
        }
    }

    if (mode == 0) {
        __half* out = (__half*)outv;
        #pragma unroll
        for (int mi = 0; mi < 4; mi++) {
            #pragma unroll
            for (int hf = 0; hf < 2; hf++) {
                const int m = row0 + wm0 + mi * 16 + qrow + hf * 8;
                const int bi = m >> 12;
                const int t  = m & (SEQ - 1);
                #pragma unroll
                for (int ni = 0; ni < 4; ni++) {
                    const int n = col0 + wn0 + ni * 8 + qcol * 2;
                    const int h = n >> 6;
                    const int d = n & (HDIM - 1);
                    *(uint32_t*)&out[(((size_t)bi * HEADS + h) * SEQ + t) * HDIM + d] =
                        pack_h2(c[mi][ni][hf * 2] * scale, c[mi][ni][hf * 2 + 1] * scale);
                }
            }
        }
    } else {
        float* out = (float*)outv;
        #pragma unroll
        for (int mi = 0; mi < 4; mi++) {
            #pragma unroll
            for (int hf = 0; hf < 2; hf++) {
                const int m = row0 + wm0 + mi * 16 + qrow + hf * 8;
                #pragma unroll
                for (int ni = 0; ni < 4; ni++) {
                    const int n = col0 + wn0 + ni * 8 + qcol * 2;
                    float2 bb = *(const float2*)&bias[n];
                    *(float2*)&out[(size_t)m * EMB + n] =
                        make_float2(c[mi][ni][hf * 2] + bb.x,
                                    c[mi][ni][hf * 2 + 1] + bb.y);
                }
            }
        }
    }
}

// ============================================================================
// Flash attention, fp16, ldmatrix + cp.async double-buffered K/V.
// Softmax in exp2 domain (log2e folded into Q); P via ex2.approx.f16x2.
// 8 warps / 256 threads, 128 q-rows per CTA; heavy CTAs launch first.
// ============================================================================
#define FP    72
#define FTILE (64 * FP)            // halves per tile
#define FBUFB (2 * FTILE * 2)      // bytes per (Ks,Vs) stage

__global__ __launch_bounds__(256, 2) void flash_mma(
    const __half* __restrict__ Q, const __half* __restrict__ K,
    const __half* __restrict__ V, __half* __restrict__ O)
{
    extern __shared__ __align__(16) char dynsm[];
    __half* Ks0 = (__half*)dynsm;                  // stage s at + s*2*FTILE
    __half* Vs0 = Ks0 + FTILE;
    __half* Ps  = Ks0 + 4 * FTILE;                 // Ps[grp] at + grp*FTILE

    const int qt = gridDim.x - 1 - blockIdx.x;     // heavy tiles first (LPT)
    const int bh = blockIdx.y;
    const size_t base = (size_t)bh * SEQ * HDIM;
    const __half* Qb = Q + base;
    const __half* Kb = K + base;
    const __half* Vb = V + base;

    const int tid  = threadIdx.x;
    const int wid  = tid >> 5;
    const int grp  = wid >> 2;
    const int w16  = (wid & 3) * 16;
    const int lid  = tid & 31;
    const int qrow = lid >> 2;
    const int qcol = lid & 3;
    const int q0   = qt * 128;
    const int jtmax = 2 * qt + grp;
    const int last  = 2 * qt + 1;
    const unsigned FULL = 0xffffffffu;

    // ldmatrix per-lane base addresses (stage 0; add buf*FBUFB at use)
    const int i8 = lid & 7;
    const int g1 = (lid >> 3) & 1;
    const int g2 = (lid >> 4) & 1;
    __half* Pg = Ps + grp * FTILE;
    const uint32_t paddr = cvta_smem(Pg) +
        (uint32_t)(((w16 + g1 * 8 + i8) * FP + g2 * 8) * 2);
    uint32_t kaddr[4], vaddr[4];
    {
        const uint32_t kb_ = cvta_smem(Ks0);
        const uint32_t vb_ = cvta_smem(Vs0);
        #pragma unroll
        for (int ntp = 0; ntp < 4; ntp++) {
            kaddr[ntp] = kb_ + (uint32_t)((((2 * ntp + g2) * 8 + i8) * FP + g1 * 8) * 2);
            vaddr[ntp] = vb_ + (uint32_t)(((g1 * 8 + i8) * FP + (2 * ntp + g2) * 8) * 2);
        }
    }

    const uint32_t ksb = cvta_smem(Ks0);
    const uint32_t vsb = cvta_smem(Vs0);
    auto prefetch = [&](int jt, int s) {
        #pragma unroll
        for (int l = 0; l < 2; l++) {
            int idx = tid + l * 256;       // 0..511
            int r   = idx >> 3;            // 0..63
            int c8  = (idx & 7) * 8;
            size_t g = (size_t)(jt * 64 + r) * HDIM + c8;
            uint32_t off = (uint32_t)(r * FP + c8) * 2 + s * FBUFB;
            cp16(ksb + off, &Kb[g]);
            cp16(vsb + off, &Vb[g]);
        }
    };

    prefetch(0, 0);
    CP_COMMIT();

    // ---- stage Q (pre-scaled half, log2e folded) into Ps, pull fragments ----
    #pragma unroll
    for (int l = 0; l < 4; l++) {
        int idx = tid + l * 256;           // 0..1023 uint4 slots
        int r   = idx >> 3;                // 0..127
        int c8  = (idx & 7) * 8;
        *(uint4*)&Ps[(r >> 6) * FTILE + (r & 63) * FP + c8] =
            *(const uint4*)&Qb[(size_t)(q0 + r) * HDIM + c8];
    }
    __syncthreads();

    uint32_t aq[4][4];
    #pragma unroll
    for (int ks = 0; ks < 4; ks++)
        ldm_x4(aq[ks][0], aq[ks][1], aq[ks][2], aq[ks][3], paddr + ks * 32);

    float o[8][4];
    #pragma unroll
    for (int nt = 0; nt < 8; nt++)
        #pragma unroll
        for (int f = 0; f < 4; f++) o[nt][f] = 0.f;
    float m_lo = -INFINITY, m_hi = -INFINITY, l_lo = 0.f, l_hi = 0.f;

    int buf = 0;
    for (int jt = 0; jt <= last; jt++) {
        if (jt < last) {
            prefetch(jt + 1, buf ^ 1);
            CP_COMMIT();
            CP_WAIT(1);
        } else {
            CP_WAIT(0);
        }
        __syncthreads();

        if (jt <= jtmax) {
            const uint32_t boff = buf * FBUFB;

            // ---- S = Q K^T (log2 domain) ----
            float c[8][4];
            #pragma unroll
            for (int nt = 0; nt < 8; nt++)
                #pragma unroll
                for (int f = 0; f < 4; f++) c[nt][f] = 0.f;

            #pragma unroll
            for (int ks = 0; ks < 4; ks++) {
                #pragma unroll
                for (int ntp = 0; ntp < 4; ntp++) {
                    uint32_t b0, b1, b2, b3;
                    ldm_x4(b0, b1, b2, b3, kaddr[ntp] + boff + ks * 32);
                    mma_fp16(c[2*ntp][0], c[2*ntp][1], c[2*ntp][2], c[2*ntp][3],
                             aq[ks][0], aq[ks][1], aq[ks][2], aq[ks][3], b0, b1);
                    mma_fp16(c[2*ntp+1][0], c[2*ntp+1][1], c[2*ntp+1][2], c[2*ntp+1][3],
                             aq[ks][0], aq[ks][1], aq[ks][2], aq[ks][3], b2, b3);
                }
            }

            // ---- causal mask (diagonal tile of this group) ----
            if (jt == jtmax) {
                #pragma unroll
                for (int nt = 0; nt < 8; nt++) {
                    #pragma unroll
                    for (int f = 0; f < 4; f++) {
                        int kloc = nt * 8 + 2 * qcol + (f & 1);
                        int qloc = w16 + qrow + ((f >> 1) * 8);
                        if (kloc > qloc) c[nt][f] = -INFINITY;
                    }
                }
            }

            // ---- online softmax (exp2 domain, fp16x2 MUFU) ----
            float tl = -INFINITY, th = -INFINITY;
            #pragma unroll
            for (int nt = 0; nt < 8; nt++) {
                tl = fmaxf(tl, fmaxf(c[nt][0], c[nt][1]));
                th = fmaxf(th, fmaxf(c[nt][2], c[nt][3]));
            }
            tl = fmaxf(tl, __shfl_xor_sync(FULL, tl, 1, 4));
            tl = fmaxf(tl, __shfl_xor_sync(FULL, tl, 2, 4));
            th = fmaxf(th, __shfl_xor_sync(FULL, th, 1, 4));
            th = fmaxf(th, __shfl_xor_sync(FULL, th, 2, 4));

            float mn_lo = fmaxf(m_lo, tl);
            float mn_hi = fmaxf(m_hi, th);
            float f_lo = ex2f(m_lo - mn_lo);
            float f_hi = ex2f(m_hi - mn_hi);

            float rs_lo = 0.f, rs_hi = 0.f;
            #pragma unroll
            for (int nt = 0; nt < 8; nt++) {
                uint32_t e01 = h2exp2(pack_h2(c[nt][0] - mn_lo, c[nt][1] - mn_lo));
                uint32_t e23 = h2exp2(pack_h2(c[nt][2] - mn_hi, c[nt][3] - mn_hi));
                int col = nt * 8 + 2 * qcol;
                *(uint32_t*)&Pg[(w16 + qrow) * FP + col]     = e01;
                *(uint32_t*)&Pg[(w16 + qrow + 8) * FP + col] = e23;
                float2 f01 = __half22float2(*(__half2*)&e01);
                float2 f23 = __half22float2(*(__half2*)&e23);
                rs_lo += f01.x + f01.y;
                rs_hi += f23.x + f23.y;
            }
            rs_lo += __shfl_xor_sync(FULL, rs_lo, 1, 4);
            rs_lo += __shfl_xor_sync(FULL, rs_lo, 2, 4);
            rs_hi += __shfl_xor_sync(FULL, rs_hi, 1, 4);
            rs_hi += __shfl_xor_sync(FULL, rs_hi, 2, 4);

            l_lo = l_lo * f_lo + rs_lo;
            l_hi = l_hi * f_hi + rs_hi;
            m_lo = mn_lo;
            m_hi = mn_hi;
            #pragma unroll
            for (int nt = 0; nt < 8; nt++) {
                o[nt][0] *= f_lo; o[nt][1] *= f_lo;
                o[nt][2] *= f_hi; o[nt][3] *= f_hi;
            }
            __syncwarp();      // Ps rows warp-private: order STS -> ldmatrix

            // ---- O += P V ----
            #pragma unroll
            for (int ks = 0; ks < 4; ks++) {
                uint32_t a0, a1, a2, a3;
                ldm_x4(a0, a1, a2, a3, paddr + ks * 32);
                #pragma unroll
                for (int ntp = 0; ntp < 4; ntp++) {
                    uint32_t v0, v1, v2, v3;
                    ldm_x4_t(v0, v1, v2, v3, vaddr[ntp] + boff + ks * (16 * FP * 2));
                    mma_fp16(o[2*ntp][0], o[2*ntp][1], o[2*ntp][2], o[2*ntp][3],
                             a0, a1, a2, a3, v0, v1);
                    mma_fp16(o[2*ntp+1][0], o[2*ntp+1][1], o[2*ntp+1][2], o[2*ntp+1][3],
                             a0, a1, a2, a3, v2, v3);
                }
            }
        }
        __syncthreads();
        buf ^= 1;
    }

    // ---- epilogue: write half (B,T,E) ----
    const float inv_lo = 1.f / l_lo;
    const float inv_hi = 1.f / l_hi;
    const int b = bh >> 4;
    const int h = bh & (HEADS - 1);
    const int row_lo = q0 + grp * 64 + w16 + qrow;
    const int row_hi = row_lo + 8;
    #pragma unroll
    for (int nt = 0; nt < 8; nt++) {
        const int e = h * HDIM + nt * 8 + 2 * qcol;
        *(uint32_t*)&O[((size_t)(b * SEQ) + row_lo) * EMB + e] =
            pack_h2(o[nt][0] * inv_lo, o[nt][1] * inv_lo);
        *(uint32_t*)&O[((size_t)(b * SEQ) + row_hi) * EMB + e] =
            pack_h2(o[nt][2] * inv_hi, o[nt][3] * inv_hi);
    }
}

// ---------------- launch -----------------------------------------------------
extern "C" void kernel_launch(void* const* d_in, const int* in_sizes, int n_in,
                              void* d_out, int out_size)
{
    const float* x  = (const float*)d_in[0];
    const float* Wq = (const float*)d_in[1];
    const float* Wk = (const float*)d_in[2];
    const float* Wv = (const float*)d_in[3];
    const float* Wo = (const float*)d_in[4];
    const float* bo = (const float*)d_in[5];
    float* out = (float*)d_out;

    __half *Qp, *Kp, *Vp, *Ap, *xh, *Wh;
    cudaGetSymbolAddress((void**)&Qp, g_Qh);
    cudaGetSymbolAddress((void**)&Kp, g_Kh);
    cudaGetSymbolAddress((void**)&Vp, g_Vh);
    cudaGetSymbolAddress((void**)&Ap, g_AOh);
    cudaGetSymbolAddress((void**)&xh, g_xh);
    cudaGetSymbolAddress((void**)&Wh, g_Wh);

    const int nW = EMB * EMB;
    cvt_all<<<(NX + 4 * NWEL) / (256 * 16), 256>>>(x, Wq, Wk, Wv, Wo, xh, Wh);

    cudaFuncSetAttribute(gemm_h, cudaFuncAttributeMaxDynamicSharedMemorySize, GSMEM);
    dim3 gg(EMB / 128, MROWS / 128);   // (8, 64)
    const float qscale = 0.125f * 1.4426950408889634f;   // fold log2e
    gemm_h<<<gg, 256, GSMEM>>>(xh, Wh + 0 * (size_t)nW, nullptr, Qp, 0, qscale);
    gemm_h<<<gg, 256, GSMEM>>>(xh, Wh + 1 * (size_t)nW, nullptr, Kp, 0, 1.0f);
    gemm_h<<<gg, 256, GSMEM>>>(xh, Wh + 2 * (size_t)nW, nullptr, Vp, 0, 1.0f);

    const int fsm = 6 * FTILE * 2;     // 55296 B
    cudaFuncSetAttribute(flash_mma, cudaFuncAttributeMaxDynamicSharedMemorySize, fsm);
    flash_mma<<<dim3(SEQ / 128, BATCH * HEADS), 256, fsm>>>(Qp, Kp, Vp, Ap);

    gemm_h<<<gg, 256, GSMEM>>>(Ap, Wh + 3 * (size_t)nW, bo, out, 1, 1.0f);
}